// round 14
// baseline (speedup 1.0000x reference)
#include <cuda_runtime.h>
#include <cuda_bf16.h>
#include <math.h>
#include <stdint.h>

#define LTOT   1360
#define BATCH  4
#define NROWS  (BATCH*LTOT)          // 5440
#define L2SZ   ((size_t)LTOT*LTOT)
#define SIMB   (1048576 + 65536)
#define LPAD   1408
#define NBH    (BATCH*8)
#define NJT    22

// weight arena element offsets
#define WOFF_DOWN 0
#define WOFF_UP   262144
#define WOFF_CONV 524288
#define WOFF_QKV  3670016
#define WOFF_FC   6815744
#define WOFF_FFN1 7864320
#define WOFF_FFN2 8388608
#define WTOT      8912896

typedef __nv_bfloat16 bf16;
typedef unsigned int u32;

// ---------------- static device scratch ----------------
__device__ float g_c1[BATCH*256*512];
__device__ float g_c2[BATCH*64*512];
__device__ float g_c3[BATCH*16*512];
__device__ float g_pyr[BATCH*336*512];
__device__ float g_x[NROWS*512];
__device__ float g_q[NROWS*512];
__device__ float g_k[NROWS*512];
__device__ float g_v[NROWS*512];
__device__ float g_q2[NROWS*512];
__device__ float g_k2[NROWS*512];
__device__ float g_v2[NROWS*512];
__device__ float g_fc[NROWS*512];
__device__ float g_fc2[NROWS*512];
__device__ float g_xn[NROWS*512];
__device__ float g_wc[3*2048*512];
__device__ float g_sim[(size_t)BATCH*SIMB];
__device__ unsigned char g_sm[(size_t)BATCH*LTOT*LTOT];
// bf16 hi/lo operand buffers
__device__ bf16 g_wHI[WTOT];
__device__ bf16 g_wLO[WTOT];
__device__ bf16 g_xhi[NROWS*512];
__device__ bf16 g_xlo[NROWS*512];
__device__ bf16 g_xnhi[NROWS*512];
__device__ bf16 g_xnlo[NROWS*512];
__device__ bf16 g_oohi[2*NROWS*512];
__device__ bf16 g_oolo[2*NROWS*512];
__device__ bf16 g_hhi[NROWS*512];
__device__ bf16 g_hlo[NROWS*512];
// attention buffers
__device__ bf16 g_QH[(size_t)NBH*LPAD*64];
__device__ bf16 g_QL[(size_t)NBH*LPAD*64];
__device__ bf16 g_KH[(size_t)NBH*LPAD*64];
__device__ bf16 g_KL[(size_t)NBH*LPAD*64];
__device__ bf16 g_VTH[(size_t)NBH*64*LPAD];
__device__ bf16 g_VTL[(size_t)NBH*64*LPAD];

__device__ __forceinline__ void wr_hl(bf16* hi, bf16* lo, size_t idx, float v) {
    bf16 h = __float2bfloat16(v);
    hi[idx] = h;
    lo[idx] = __float2bfloat16(v - __bfloat162float(h));
}

// ---------------- fp32 -> bf16 hi/lo (flat) ----------------
__global__ void k_cvtA(const float* __restrict__ s, bf16* __restrict__ hi,
                       bf16* __restrict__ lo, int n4) {
    int i = blockIdx.x*blockDim.x + threadIdx.x;
    if (i >= n4) return;
    float4 v = ((const float4*)s)[i];
    bf16 h0=__float2bfloat16(v.x), h1=__float2bfloat16(v.y),
         h2=__float2bfloat16(v.z), h3=__float2bfloat16(v.w);
    bf16 l0=__float2bfloat16(v.x-__bfloat162float(h0)),
         l1=__float2bfloat16(v.y-__bfloat162float(h1)),
         l2=__float2bfloat16(v.z-__bfloat162float(h2)),
         l3=__float2bfloat16(v.w-__bfloat162float(h3));
    uint2 hp = make_uint2((u32)__bfloat16_as_ushort(h0) | ((u32)__bfloat16_as_ushort(h1)<<16),
                          (u32)__bfloat16_as_ushort(h2) | ((u32)__bfloat16_as_ushort(h3)<<16));
    uint2 lp = make_uint2((u32)__bfloat16_as_ushort(l0) | ((u32)__bfloat16_as_ushort(l1)<<16),
                          (u32)__bfloat16_as_ushort(l2) | ((u32)__bfloat16_as_ushort(l3)<<16));
    ((uint2*)hi)[i] = hp;
    ((uint2*)lo)[i] = lp;
}

// ---------------- fp32 [K][N] -> bf16 hi/lo transposed [N][K] ----------------
__device__ __forceinline__ void cvtB_body(const float* __restrict__ src,
        bf16* __restrict__ hi, bf16* __restrict__ lo, int K, int N) {
    __shared__ float t[32][33];
    int tx = threadIdx.x, ty = threadIdx.y;
    int n0 = blockIdx.x*32, k0 = blockIdx.y*32;
    #pragma unroll
    for (int i = 0; i < 4; i++)
        t[ty + i*8][tx] = src[(size_t)(k0 + ty + i*8)*N + n0 + tx];
    __syncthreads();
    #pragma unroll
    for (int i = 0; i < 4; i++) {
        float v = t[tx][ty + i*8];
        int n = n0 + ty + i*8, kk = k0 + tx;
        wr_hl(hi, lo, (size_t)n*K + kk, v);
    }
}
__global__ void k_cvtB(const float* __restrict__ src, bf16* hi, bf16* lo, int K, int N) {
    cvtB_body(src, hi, lo, K, N);
}
__global__ void k_cvtB_multi(const float* __restrict__ src, bf16* hi, bf16* lo,
                             int K, int N) {
    size_t off = (size_t)blockIdx.z*K*N;
    cvtB_body(src + off, hi + off, lo + off, K, N);
}
__global__ void k_cvtW_qkv12(const float* __restrict__ Wq, const float* __restrict__ Wk,
                             const float* __restrict__ Wv, bf16* hi, bf16* lo) {
    int z = blockIdx.z;
    int l = z/6, rem = z%6, s = rem/3, c = rem%3;
    const float* base = ((c==0)?Wq:(c==1)?Wk:Wv) + ((size_t)(l*2+s))*262144;
    cvtB_body(base, hi + (size_t)z*262144, lo + (size_t)z*262144, 512, 512);
}

// ---------------- bf16x3 MMA GEMM with cp.async double-buffer ----------------
__device__ __forceinline__ void mma16816(float* d, const u32* a, const u32* b) {
    asm volatile(
        "mma.sync.aligned.m16n8k16.row.col.f32.bf16.bf16.f32 "
        "{%0,%1,%2,%3}, {%4,%5,%6,%7}, {%8,%9}, {%0,%1,%2,%3};"
        : "+f"(d[0]), "+f"(d[1]), "+f"(d[2]), "+f"(d[3])
        : "r"(a[0]), "r"(a[1]), "r"(a[2]), "r"(a[3]), "r"(b[0]), "r"(b[1]));
}
#define AP 40
#define ABUF (128*AP)
#define BBUF (64*AP)
#define BUFELEM (2*ABUF + 2*BBUF)
#define DSMEM (2*BUFELEM*2)

__device__ __forceinline__ u32 sm32(const void* p) {
    return (u32)__cvta_generic_to_shared(p);
}
__device__ __forceinline__ void cp16(u32 dst, const void* src, int bytes) {
    asm volatile("cp.async.ca.shared.global [%0], [%1], 16, %2;"
                 :: "r"(dst), "l"(src), "r"(bytes));
}

#define MG_LOADC(kc, bsel)                                                     \
    {                                                                          \
        bf16* base = dsm + (bsel)*BUFELEM;                                     \
        _Pragma("unroll")                                                      \
        for (int s = 0; s < 2; s++) {                                          \
            int slot = s*256 + tid;                                            \
            int r = slot >> 2, k16 = (slot & 3) << 3;                          \
            int gr = row0 + r;                                                 \
            int ok = (gr < M) ? 16 : 0;                                        \
            size_t go = (size_t)(gr < M ? gr : 0)*K + (kc) + k16;              \
            cp16(sm32(base + r*AP + k16), Ahi + go, ok);                       \
            cp16(sm32(base + ABUF + r*AP + k16), Alo + go, ok);                \
        }                                                                      \
        {                                                                      \
            int r = tid >> 2, k16 = (tid & 3) << 3;                            \
            size_t go = (size_t)(col0 + r)*K + (kc) + k16;                     \
            cp16(sm32(base + 2*ABUF + r*AP + k16), Bhi + go, 16);              \
            cp16(sm32(base + 2*ABUF + BBUF + r*AP + k16), Blo + go, 16);       \
        }                                                                      \
        asm volatile("cp.async.commit_group;" ::: "memory");                   \
    }

#define MG_MAINLOOP()                                                          \
    MG_LOADC(0, 0);                                                            \
    int buf = 0;                                                               \
    for (int kc = 0; kc < K; kc += 32) {                                       \
        bool more = (kc + 32) < K;                                             \
        if (more) {                                                            \
            MG_LOADC(kc + 32, buf ^ 1);                                        \
            asm volatile("cp.async.wait_group 1;" ::: "memory");               \
        } else {                                                               \
            asm volatile("cp.async.wait_group 0;" ::: "memory");               \
        }                                                                      \
        __syncthreads();                                                       \
        const bf16* As0 = dsm + buf*BUFELEM;                                   \
        const bf16* As1 = As0 + ABUF;                                          \
        const bf16* Bs0 = As0 + 2*ABUF;                                        \
        const bf16* Bs1 = Bs0 + BBUF;                                          \
        _Pragma("unroll")                                                      \
        for (int ks = 0; ks < 32; ks += 16) {                                  \
            u32 ah[2][4], al[2][4], bh[4][2], bl[4][2];                        \
            _Pragma("unroll")                                                  \
            for (int mt = 0; mt < 2; mt++) {                                   \
                int ar = (wm*32 + mt*16 + g)*AP + ks + qp*2;                   \
                int ar8 = ar + 8*AP;                                           \
                ah[mt][0] = *(const u32*)&As0[ar];                             \
                ah[mt][1] = *(const u32*)&As0[ar8];                            \
                ah[mt][2] = *(const u32*)&As0[ar + 8];                         \
                ah[mt][3] = *(const u32*)&As0[ar8 + 8];                        \
                al[mt][0] = *(const u32*)&As1[ar];                             \
                al[mt][1] = *(const u32*)&As1[ar8];                            \
                al[mt][2] = *(const u32*)&As1[ar + 8];                         \
                al[mt][3] = *(const u32*)&As1[ar8 + 8];                        \
            }                                                                  \
            _Pragma("unroll")                                                  \
            for (int nt = 0; nt < 4; nt++) {                                   \
                int br = (wn*32 + nt*8 + g)*AP + ks + qp*2;                    \
                bh[nt][0] = *(const u32*)&Bs0[br];                             \
                bh[nt][1] = *(const u32*)&Bs0[br + 8];                         \
                bl[nt][0] = *(const u32*)&Bs1[br];                             \
                bl[nt][1] = *(const u32*)&Bs1[br + 8];                         \
            }                                                                  \
            _Pragma("unroll")                                                  \
            for (int mt = 0; mt < 2; mt++)                                     \
                _Pragma("unroll")                                              \
                for (int nt = 0; nt < 4; nt++) {                               \
                    mma16816(acc[mt][nt], ah[mt], bh[nt]);                     \
                    mma16816(acc[mt][nt], ah[mt], bl[nt]);                     \
                    mma16816(acc[mt][nt], al[mt], bh[nt]);                     \
                }                                                              \
        }                                                                      \
        __syncthreads();                                                       \
        buf ^= 1;                                                              \
    }

// mode: 0 none, 1 relu, 2 scale+elu. C/Chi may be null.
__device__ void mg_body(const bf16* __restrict__ Ahi, const bf16* __restrict__ Alo,
                        const bf16* __restrict__ Bhi, const bf16* __restrict__ Blo,
                        float* __restrict__ C, bf16* __restrict__ Chi,
                        bf16* __restrict__ Clo, const float* __restrict__ bias,
                        int M, int N, int K, int mode, int ldc) {
    extern __shared__ bf16 dsm[];
    int tid = threadIdx.x, wid = tid >> 5, lane = tid & 31;
    int wm = wid >> 1, wn = wid & 1, g = lane >> 2, qp = lane & 3;
    int row0 = blockIdx.y << 7, col0 = blockIdx.x << 6;
    float acc[2][4][4] = {};
    MG_MAINLOOP();
    #pragma unroll
    for (int mt = 0; mt < 2; mt++) {
        #pragma unroll
        for (int half = 0; half < 2; half++) {
            int r = row0 + wm*32 + mt*16 + g + half*8;
            if (r >= M) continue;
            #pragma unroll
            for (int nt = 0; nt < 4; nt++) {
                int cl = col0 + wn*32 + nt*8 + qp*2;
                float v0 = acc[mt][nt][half*2 + 0], v1 = acc[mt][nt][half*2 + 1];
                if (bias) { v0 += bias[cl]; v1 += bias[cl + 1]; }
                if (mode == 1) { v0 = fmaxf(v0, 0.f); v1 = fmaxf(v1, 0.f); }
                else if (mode == 2) {
                    v0 *= 0.9999950000374997f; if (v0 <= 0.f) v0 = expm1f(v0);
                    v1 *= 0.9999950000374997f; if (v1 <= 0.f) v1 = expm1f(v1);
                }
                size_t ci = (size_t)r*ldc + cl;
                if (C) *(float2*)&C[ci] = make_float2(v0, v1);
                if (Chi) {
                    bf16 h0 = __float2bfloat16(v0), h1 = __float2bfloat16(v1);
                    bf16 l0 = __float2bfloat16(v0 - __bfloat162float(h0));
                    bf16 l1 = __float2bfloat16(v1 - __bfloat162float(h1));
                    *(u32*)&Chi[ci] = (u32)__bfloat16_as_ushort(h0) |
                                      ((u32)__bfloat16_as_ushort(h1) << 16);
                    *(u32*)&Clo[ci] = (u32)__bfloat16_as_ushort(l0) |
                                      ((u32)__bfloat16_as_ushort(l1) << 16);
                }
            }
        }
    }
}

__global__ void __launch_bounds__(256) k_mgemm(
        const bf16* Ahi, const bf16* Alo, const bf16* Bhi, const bf16* Blo,
        float* C, bf16* Chi, bf16* Clo, const float* bias,
        int M, int N, int K, int mode) {
    mg_body(Ahi, Alo, Bhi, Blo, C, Chi, Clo, bias, M, N, K, mode, N);
}
__global__ void __launch_bounds__(256) k_mgemm_qkv(
        const bf16* Ahi, const bf16* Alo, const bf16* Bhi, const bf16* Blo,
        float* q, float* k, float* v, float* q2, float* k2, float* v2,
        int M, int N, int K) {
    int z = blockIdx.z;
    size_t bo = (size_t)z*262144;
    float* C = (z==0)?q:(z==1)?k:(z==2)?v:(z==3)?q2:(z==4)?k2:v2;
    mg_body(Ahi, Alo, Bhi + bo, Blo + bo, C, nullptr, nullptr, nullptr, M, N, K, 0, N);
}
__global__ void __launch_bounds__(256) k_mgemm_fc(
        const bf16* Ahi, const bf16* Alo, const bf16* Bhi, const bf16* Blo,
        const float* fcb, size_t lo_t, size_t lo_s,
        float* ft, float* fs, int M, int N, int K) {
    int z = blockIdx.z;
    size_t ao = (size_t)z*NROWS*512, bo = (size_t)z*262144;
    mg_body(Ahi + ao, Alo + ao, Bhi + bo, Blo + bo, z ? fs : ft, nullptr, nullptr,
            fcb + (z ? lo_s : lo_t), M, N, K, 0, N);
}
__global__ void __launch_bounds__(256) k_mgemm_sim(
        const bf16* Ahi, const bf16* Alo, int startRow, int n, size_t lvloff,
        float* simbuf) {
    int b = blockIdx.z;
    size_t ao = ((size_t)(b*LTOT + startRow))*512;
    float* C = simbuf + (size_t)b*SIMB + lvloff;
    mg_body(Ahi + ao, Alo + ao, Ahi + ao, Alo + ao, C, nullptr, nullptr, nullptr,
            n, n, 512, 0, n);
}

// ================= flash semantic attention (pitch FAP=72) =================
// smem (bf16 elems): Q 128x72 hi/lo | 2 stages x (K 64x72 hi/lo + V 64x72 hi/lo) | P 128x72 hi/lo
#define FAP 72
#define FQ_HI 0
#define FQ_LO 9216
#define FSTG(b) (18432 + (b)*18432)
#define FK_HI(b) (FSTG(b))
#define FK_LO(b) (FSTG(b) + 4608)
#define FV_HI(b) (FSTG(b) + 9216)
#define FV_LO(b) (FSTG(b) + 13824)
#define FP_HI 55296
#define FP_LO 64512
#define FA_SMEM (73728*2)   // 147,456 bytes

__global__ void __launch_bounds__(256) k_fattn(
        const bf16* __restrict__ QHg, const bf16* __restrict__ QLg,
        const bf16* __restrict__ KHg, const bf16* __restrict__ KLg,
        const bf16* __restrict__ VTHg, const bf16* __restrict__ VTLg,
        const unsigned char* __restrict__ smask,
        bf16* __restrict__ Ohi, bf16* __restrict__ Olo) {
    extern __shared__ bf16 dsm[];
    __shared__ float psm[128][2];
    int tid = threadIdx.x, wid = tid >> 5, lane = tid & 31;
    int wm = wid >> 1, wn = wid & 1, g = lane >> 2, qp = lane & 3;
    int row0 = blockIdx.x << 7;
    int bh = blockIdx.y, b = bh >> 3, h = bh & 7;
    const bf16* QH = QHg + (size_t)bh*LPAD*64;
    const bf16* QL = QLg + (size_t)bh*LPAD*64;
    const bf16* KH = KHg + (size_t)bh*LPAD*64;
    const bf16* KL = KLg + (size_t)bh*LPAD*64;
    const bf16* VTH = VTHg + (size_t)bh*64*LPAD;
    const bf16* VTL = VTLg + (size_t)bh*64*LPAD;

    // stage Q tile (128 rows x 64 k, 8 chunks of 8 per row)
    #pragma unroll
    for (int s = 0; s < 4; s++) {
        int slot = s*256 + tid;
        int r = slot >> 3, k8 = (slot & 7) << 3;
        size_t go = (size_t)(row0 + r)*64 + k8;
        cp16(sm32(dsm + FQ_HI + r*FAP + k8), QH + go, 16);
        cp16(sm32(dsm + FQ_LO + r*FAP + k8), QL + go, 16);
    }
    // stage K/V tile 0 (64 rows x 64)
    #pragma unroll
    for (int s = 0; s < 2; s++) {
        int slot = s*256 + tid;
        int r = slot >> 3, k8 = (slot & 7) << 3;
        size_t gk = (size_t)r*64 + k8;
        cp16(sm32(dsm + FK_HI(0) + r*FAP + k8), KH + gk, 16);
        cp16(sm32(dsm + FK_LO(0) + r*FAP + k8), KL + gk, 16);
        size_t gv = (size_t)r*LPAD + k8;
        cp16(sm32(dsm + FV_HI(0) + r*FAP + k8), VTH + gv, 16);
        cp16(sm32(dsm + FV_LO(0) + r*FAP + k8), VTL + gv, 16);
    }
    asm volatile("cp.async.commit_group;" ::: "memory");

    float acc_o[2][4][4] = {};
    float rsum[2][2] = {};
    int buf = 0;
    for (int kt = 0; kt < NJT; kt++) {
        if (kt + 1 < NJT) {
            int nb = buf ^ 1;
            int jb = (kt + 1) << 6;
            #pragma unroll
            for (int s = 0; s < 2; s++) {
                int slot = s*256 + tid;
                int r = slot >> 3, k8 = (slot & 7) << 3;
                size_t gk = (size_t)(jb + r)*64 + k8;
                cp16(sm32(dsm + FK_HI(nb) + r*FAP + k8), KH + gk, 16);
                cp16(sm32(dsm + FK_LO(nb) + r*FAP + k8), KL + gk, 16);
                size_t gv = (size_t)r*LPAD + jb + k8;
                cp16(sm32(dsm + FV_HI(nb) + r*FAP + k8), VTH + gv, 16);
                cp16(sm32(dsm + FV_LO(nb) + r*FAP + k8), VTL + gv, 16);
            }
            asm volatile("cp.async.commit_group;" ::: "memory");
            asm volatile("cp.async.wait_group 1;" ::: "memory");
        } else {
            asm volatile("cp.async.wait_group 0;" ::: "memory");
        }
        __syncthreads();   // K/V visible; prior P fully consumed

        // ---- S = Q K^T (128x64) ----
        float acc[2][4][4] = {};
        {
            const bf16* As0 = dsm + FQ_HI;
            const bf16* As1 = dsm + FQ_LO;
            const bf16* Bs0 = dsm + FK_HI(buf);
            const bf16* Bs1 = dsm + FK_LO(buf);
            #pragma unroll
            for (int ks = 0; ks < 64; ks += 16) {
                u32 ah[2][4], al[2][4], bh[4][2], bl[4][2];
                #pragma unroll
                for (int mt = 0; mt < 2; mt++) {
                    int ar = (wm*32 + mt*16 + g)*FAP + ks + qp*2;
                    int ar8 = ar + 8*FAP;
                    ah[mt][0] = *(const u32*)&As0[ar];     ah[mt][1] = *(const u32*)&As0[ar8];
                    ah[mt][2] = *(const u32*)&As0[ar + 8]; ah[mt][3] = *(const u32*)&As0[ar8 + 8];
                    al[mt][0] = *(const u32*)&As1[ar];     al[mt][1] = *(const u32*)&As1[ar8];
                    al[mt][2] = *(const u32*)&As1[ar + 8]; al[mt][3] = *(const u32*)&As1[ar8 + 8];
                }
                #pragma unroll
                for (int nt = 0; nt < 4; nt++) {
                    int br = (wn*32 + nt*8 + g)*FAP + ks + qp*2;
                    bh[nt][0] = *(const u32*)&Bs0[br]; bh[nt][1] = *(const u32*)&Bs0[br + 8];
                    bl[nt][0] = *(const u32*)&Bs1[br]; bl[nt][1] = *(const u32*)&Bs1[br + 8];
                }
                #pragma unroll
                for (int mt = 0; mt < 2; mt++)
                    #pragma unroll
                    for (int nt = 0; nt < 4; nt++) {
                        mma16816(acc[mt][nt], ah[mt], bh[nt]);
                        mma16816(acc[mt][nt], ah[mt], bl[nt]);
                        mma16816(acc[mt][nt], al[mt], bh[nt]);
                    }
            }
        }
        // ---- exp + mask -> P smem, accumulate row sums ----
        int jb = kt << 6;
        #pragma unroll
        for (int mt = 0; mt < 2; mt++) {
            #pragma unroll
            for (int half = 0; half < 2; half++) {
                int rl = wm*32 + mt*16 + g + half*8;
                int r = row0 + rl;
                bool rok = (r < LTOT);
                const unsigned char* mrow = smask + ((size_t)b*LTOT + (rok ? r : 0))*LTOT;
                #pragma unroll
                for (int nt = 0; nt < 4; nt++) {
                    int cl = wn*32 + nt*8 + qp*2;
                    int jg = jb + cl;
                    float e0 = 0.f, e1 = 0.f;
                    if (rok) {
                        if (jg < LTOT && !mrow[jg])
                            e0 = __expf(acc[mt][nt][half*2 + 0]*0.125f);
                        if (jg + 1 < LTOT && !mrow[jg + 1])
                            e1 = __expf(acc[mt][nt][half*2 + 1]*0.125f);
                    }
                    rsum[mt][half] += e0 + e1;
                    bf16 h0 = __float2bfloat16(e0), h1 = __float2bfloat16(e1);
                    bf16 l0 = __float2bfloat16(e0 - __bfloat162float(h0));
                    bf16 l1 = __float2bfloat16(e1 - __bfloat162float(h1));
                    int pi = rl*FAP + cl;
                    *(u32*)&dsm[FP_HI + pi] = (u32)__bfloat16_as_ushort(h0) |
                                              ((u32)__bfloat16_as_ushort(h1) << 16);
                    *(u32*)&dsm[FP_LO + pi] = (u32)__bfloat16_as_ushort(l0) |
                                              ((u32)__bfloat16_as_ushort(l1) << 16);
                }
            }
        }
        __syncthreads();   // P visible
        // ---- O += P V (A = P [128x64 j], B = V^T [64 d][64 j]) ----
        {
            const bf16* As0 = dsm + FP_HI;
            const bf16* As1 = dsm + FP_LO;
            const bf16* Bs0 = dsm + FV_HI(buf);
            const bf16* Bs1 = dsm + FV_LO(buf);
            #pragma unroll
            for (int ks = 0; ks < 64; ks += 16) {
                u32 ah[2][4], al[2][4], bh[4][2], bl[4][2];
                #pragma unroll
                for (int mt = 0; mt < 2; mt++) {
                    int ar = (wm*32 + mt*16 + g)*FAP + ks + qp*2;
                    int ar8 = ar + 8*FAP;
                    ah[mt][0] = *(const u32*)&As0[ar];     ah[mt][1] = *(const u32*)&As0[ar8];
                    ah[mt][2] = *(const u32*)&As0[ar + 8]; ah[mt][3] = *(const u32*)&As0[ar8 + 8];
                    al[mt][0] = *(const u32*)&As1[ar];     al[mt][1] = *(const u32*)&As1[ar8];
                    al[mt][2] = *(const u32*)&As1[ar + 8]; al[mt][3] = *(const u32*)&As1[ar8 + 8];
                }
                #pragma unroll
                for (int nt = 0; nt < 4; nt++) {
                    int br = (wn*32 + nt*8 + g)*FAP + ks + qp*2;
                    bh[nt][0] = *(const u32*)&Bs0[br]; bh[nt][1] = *(const u32*)&Bs0[br + 8];
                    bl[nt][0] = *(const u32*)&Bs1[br]; bl[nt][1] = *(const u32*)&Bs1[br + 8];
                }
                #pragma unroll
                for (int mt = 0; mt < 2; mt++)
                    #pragma unroll
                    for (int nt = 0; nt < 4; nt++) {
                        mma16816(acc_o[mt][nt], ah[mt], bh[nt]);
                        mma16816(acc_o[mt][nt], ah[mt], bl[nt]);
                        mma16816(acc_o[mt][nt], al[mt], bh[nt]);
                    }
            }
        }
        __syncthreads();   // P consumed before next overwrite
        buf ^= 1;
    }
    // ---- row-sum reduce: qp via shfl, wn via smem ----
    #pragma unroll
    for (int mt = 0; mt < 2; mt++)
        #pragma unroll
        for (int half = 0; half < 2; half++) {
            float v = rsum[mt][half];
            v += __shfl_xor_sync(0xffffffffu, v, 1);
            v += __shfl_xor_sync(0xffffffffu, v, 2);
            if (qp == 0) psm[wm*32 + mt*16 + half*8 + g][wn] = v;
        }
    __syncthreads();
    #pragma unroll
    for (int mt = 0; mt < 2; mt++) {
        #pragma unroll
        for (int half = 0; half < 2; half++) {
            int rl = wm*32 + mt*16 + g + half*8;
            int r = row0 + rl;
            if (r >= LTOT) continue;
            float inv = 1.f / (psm[rl][0] + psm[rl][1]);
            size_t base = ((size_t)(b*LTOT + r))*512 + h*64;
            #pragma unroll
            for (int nt = 0; nt < 4; nt++) {
                int cl = wn*32 + nt*8 + qp*2;
                float v0 = acc_o[mt][nt][half*2 + 0]*inv;
                float v1 = acc_o[mt][nt][half*2 + 1]*inv;
                bf16 h0 = __float2bfloat16(v0), h1 = __float2bfloat16(v1);
                bf16 l0 = __float2bfloat16(v0 - __bfloat162float(h0));
                bf16 l1 = __float2bfloat16(v1 - __bfloat162float(h1));
                *(u32*)&Ohi[base + cl] = (u32)__bfloat16_as_ushort(h0) |
                                         ((u32)__bfloat16_as_ushort(h1) << 16);
                *(u32*)&Olo[base + cl] = (u32)__bfloat16_as_ushort(l0) |
                                         ((u32)__bfloat16_as_ushort(l1) << 16);
            }
        }
    }
}

// ---------------- attention operand conversion ----------------
__global__ void k_cvt_qk(const float* __restrict__ q2, const float* __restrict__ k2,
                         bf16* QH, bf16* QL, bf16* KH, bf16* KL) {
    long idx = (long)blockIdx.x*256 + threadIdx.x;
    if (idx >= (long)NBH*LPAD*64) return;
    int d = idx & 63;
    long r_ = idx >> 6;
    int r = (int)(r_ % LPAD);
    int bh = (int)(r_ / LPAD);
    int b = bh >> 3, h = bh & 7;
    float qv = 0.f, kv = 0.f;
    if (r < LTOT) {
        size_t off = ((size_t)(b*LTOT + r))*512 + h*64 + d;
        qv = q2[off]; kv = k2[off];
    }
    wr_hl(QH, QL, idx, qv);
    wr_hl(KH, KL, idx, kv);
}
__global__ void k_cvt_vt(const float* __restrict__ v2, bf16* VTH, bf16* VTL) {
    __shared__ float t[32][33];
    int bh = blockIdx.z, b = bh >> 3, h = bh & 7;
    int j0 = blockIdx.x*32, d0 = blockIdx.y*32;
    int tx = threadIdx.x, ty = threadIdx.y;
    #pragma unroll
    for (int i = 0; i < 4; i++) {
        int j = j0 + ty + i*8;
        t[ty + i*8][tx] = (j < LTOT)
            ? v2[((size_t)(b*LTOT + j))*512 + h*64 + d0 + tx] : 0.f;
    }
    __syncthreads();
    #pragma unroll
    for (int i = 0; i < 4; i++) {
        int d = d0 + ty + i*8, j = j0 + tx;
        wr_hl(VTH, VTL, ((size_t)bh*64 + d)*LPAD + j, t[tx][ty + i*8]);
    }
}

// ---------------- reductions ----------------
__device__ __forceinline__ float block_sum256(float v) {
    __shared__ float red[8];
    int lane = threadIdx.x & 31, w = threadIdx.x >> 5;
    #pragma unroll
    for (int o = 16; o; o >>= 1) v += __shfl_xor_sync(0xffffffffu, v, o);
    if (lane == 0) red[w] = v;
    __syncthreads();
    if (w == 0) {
        float t = (lane < 8) ? red[lane] : 0.f;
        #pragma unroll
        for (int o = 4; o; o >>= 1) t += __shfl_xor_sync(0xffffffffu, t, o);
        if (lane == 0) red[0] = t;
    }
    __syncthreads();
    float r = red[0];
    __syncthreads();
    return r;
}

// ---------------- conv weight re-layout ----------------
__global__ void k_convw(const float* __restrict__ w, float* __restrict__ wm) {
    int idx = blockIdx.x*blockDim.x + threadIdx.x;
    if (idx >= 3*2048*512) return;
    int l  = idx / (2048*512);
    int r  = idx - l*2048*512;
    int kk = r >> 9, co = r & 511;
    int t  = kk >> 9, ci = kk & 511;
    wm[idx] = w[(((size_t)(l*512 + co))*512 + ci)*4 + t];
}

// ---------------- concat + LN(1e-5), emits hi/lo ----------------
__global__ void __launch_bounds__(256) k_concat_ln(
        const float* __restrict__ xe, const float* __restrict__ pyr,
        const float* __restrict__ g, const float* __restrict__ bt,
        float* __restrict__ out, bf16* ohi, bf16* olo) {
    int row = blockIdx.x;
    int b = row / LTOT, i = row % LTOT;
    const float* src = (i < 1024) ? xe + ((size_t)(b*1024 + i))*512
                                  : pyr + ((size_t)(b*336 + (i - 1024)))*512;
    int t = threadIdx.x;
    float v0 = src[t], v1 = src[t + 256];
    float mu = block_sum256(v0 + v1) * (1.f/512.f);
    float d0 = v0 - mu, d1 = v1 - mu;
    float var = block_sum256(d0*d0 + d1*d1) * (1.f/512.f);
    float rs = rsqrtf(var + 1e-5f);
    float r0 = d0*rs*g[t]       + bt[t];
    float r1 = d1*rs*g[t + 256] + bt[t + 256];
    size_t base = (size_t)row*512;
    out[base + t] = r0; out[base + t + 256] = r1;
    wr_hl(ohi, olo, base + t, r0);
    wr_hl(ohi, olo, base + t + 256, r1);
}

// ---------------- (a+res) -> LN, optional hi/lo ----------------
__global__ void __launch_bounds__(256) k_add_ln(
        const float* __restrict__ a, const float* __restrict__ res,
        const float* __restrict__ g, const float* __restrict__ bt,
        float* __restrict__ out, bf16* ohi, bf16* olo, float eps) {
    int row = blockIdx.x, t = threadIdx.x;
    const float* pa = a + (size_t)row*512;
    const float* pr = res + (size_t)row*512;
    float v0 = pa[t] + pr[t], v1 = pa[t + 256] + pr[t + 256];
    float mu = block_sum256(v0 + v1) * (1.f/512.f);
    float d0 = v0 - mu, d1 = v1 - mu;
    float var = block_sum256(d0*d0 + d1*d1) * (1.f/512.f);
    float rs = rsqrtf(var + eps);
    float r0 = d0*rs*g[t]       + bt[t];
    float r1 = d1*rs*g[t + 256] + bt[t + 256];
    size_t base = (size_t)row*512;
    out[base + t] = r0; out[base + t + 256] = r1;
    if (ohi) {
        wr_hl(ohi, olo, base + t, r0);
        wr_hl(ohi, olo, base + t + 256, r1);
    }
}

// ---------------- fused dual-LN + combine, emits hi/lo ----------------
__global__ void __launch_bounds__(256) k_lncomb(
        const float* __restrict__ fc, const float* __restrict__ fc2,
        float* __restrict__ x, bf16* xhi, bf16* xlo,
        const float* __restrict__ g, const float* __restrict__ bt,
        size_t lo_t, size_t lo_s) {
    int row = blockIdx.x, t = threadIdx.x;
    const float* pa = fc + (size_t)row*512;
    const float* pb = fc2 + (size_t)row*512;
    float* px = x + (size_t)row*512;
    float x0 = px[t], x1 = px[t + 256];
    float a0 = pa[t] + x0, a1 = pa[t + 256] + x1;
    float b0 = pb[t] + x0, b1 = pb[t + 256] + x1;
    float mu = block_sum256(a0 + a1) * (1.f/512.f);
    a0 -= mu; a1 -= mu;
    float var = block_sum256(a0*a0 + a1*a1) * (1.f/512.f);
    float rs = rsqrtf(var + 1e-6f);
    float t0 = a0*rs*g[lo_t + t]       + bt[lo_t + t];
    float t1 = a1*rs*g[lo_t + t + 256] + bt[lo_t + t + 256];
    mu = block_sum256(b0 + b1) * (1.f/512.f);
    b0 -= mu; b1 -= mu;
    var = block_sum256(b0*b0 + b1*b1) * (1.f/512.f);
    rs = rsqrtf(var + 1e-6f);
    float s0 = b0*rs*g[lo_s + t]       + bt[lo_s + t];
    float s1 = b1*rs*g[lo_s + t + 256] + bt[lo_s + t + 256];
    float r0 = (t0 + s0 + x0) * (1.f/3.f);
    float r1 = (t1 + s1 + x1) * (1.f/3.f);
    px[t] = r0; px[t + 256] = r1;
    size_t base = (size_t)row*512;
    wr_hl(xhi, xlo, base + t, r0);
    wr_hl(xhi, xlo, base + t + 256, r1);
}

// ---------------- row L2 normalize, emits hi/lo ----------------
__global__ void __launch_bounds__(256) k_rownorm(
        const float* __restrict__ x, float* __restrict__ xn,
        bf16* nhi, bf16* nlo) {
    int row = blockIdx.x, t = threadIdx.x;
    const float* p = x + (size_t)row*512;
    float v0 = p[t], v1 = p[t + 256];
    float ss = block_sum256(v0*v0 + v1*v1);
    float inv = 1.f / fmaxf(sqrtf(ss), 1e-8f);
    float r0 = v0*inv, r1 = v1*inv;
    size_t base = (size_t)row*512;
    xn[base + t] = r0; xn[base + t + 256] = r1;
    wr_hl(nhi, nlo, base + t, r0);
    wr_hl(nhi, nlo, base + t + 256, r1);
}

// ---------------- top-k select ----------------
__global__ void __launch_bounds__(256) k_topksel(
        const float* __restrict__ xn, const float* __restrict__ simbuf,
        unsigned char* __restrict__ smask) {
    int i = blockIdx.x, b = blockIdx.y, tid = threadIdx.x;
    const int starts[4] = {0,1024,1280,1344};
    const int sizes[4]  = {1024,256,64,16};
    int lev = (i<1024)?0:(i<1280)?1:(i<1344)?2:3;
    int st = starts[lev], n = sizes[lev];
    int kk = n < 32 ? n : 32;
    __shared__ float sims[1024];
    __shared__ float qrow[512];
    __shared__ float wv[8]; __shared__ int wi[8];
    unsigned char* mrow = smask + ((size_t)b*LTOT + i)*LTOT + st;
    for (int j = tid; j < n; j += 256) mrow[j] = 0;
    if (lev <= 1) {
        size_t lvloff = (lev == 0) ? 0 : 1048576;
        const float* srow = simbuf + (size_t)b*SIMB + lvloff + (size_t)(i - st)*n;
        for (int j = tid; j < n; j += 256) sims[j] = srow[j];
        __syncthreads();
    } else {
        const float* xb = xn + (size_t)b*LTOT*512;
        for (int d = tid; d < 512; d += 256) qrow[d] = xb[(size_t)i*512 + d];
        __syncthreads();
        int w = tid >> 5, lane = tid & 31;
        for (int j = w; j < n; j += 8) {
            const float* rj = xb + (size_t)(st + j)*512;
            float p = 0.f;
            #pragma unroll 4
            for (int d = lane; d < 512; d += 32) p += qrow[d]*rj[d];
            #pragma unroll
            for (int o = 16; o; o >>= 1) p += __shfl_xor_sync(0xffffffffu, p, o);
            if (lane == 0) sims[j] = p;
        }
        __syncthreads();
    }
    int w = tid >> 5, lane = tid & 31;
    for (int it = 0; it < kk; it++) {
        float bv = -3.f; int bi = n;
        for (int j = tid; j < n; j += 256) {
            float v = sims[j];
            if (v > bv) { bv = v; bi = j; }
        }
        #pragma unroll
        for (int o = 16; o; o >>= 1) {
            float ov = __shfl_xor_sync(0xffffffffu, bv, o);
            int   oi = __shfl_xor_sync(0xffffffffu, bi, o);
            if (ov > bv || (ov == bv && oi < bi)) { bv = ov; bi = oi; }
        }
        if (lane == 0) { wv[w] = bv; wi[w] = bi; }
        __syncthreads();
        if (tid == 0) {
            float fv = wv[0]; int fi = wi[0];
            #pragma unroll
            for (int z = 1; z < 8; z++)
                if (wv[z] > fv || (wv[z] == fv && wi[z] < fi)) { fv = wv[z]; fi = wi[z]; }
            mrow[fi] = 1;
            sims[fi] = -3.f;
        }
        __syncthreads();
    }
}

// ---------------- SPARSE temporal attention, emits hi/lo ----------------
__global__ void __launch_bounds__(256) k_tattn(
        const float* __restrict__ Q, const float* __restrict__ K,
        const float* __restrict__ V, bf16* __restrict__ Ohi, bf16* __restrict__ Olo) {
    int i = blockIdx.x, b = blockIdx.y;
    int h = threadIdx.x >> 5, lane = threadIdx.x & 31;
    const int starts[4] = {0,1024,1280,1344};
    const int sizes[4]  = {1024,256,64,16};
    int lev = (i<1024)?0:(i<1280)?1:(i<1344)?2:3;
    int st = starts[lev], n = sizes[lev];
    int nb[10]; int cnt = 0;
    int lo = (i-2 < st) ? st : i-2;
    int hi = (i+2 > st+n-1) ? st+n-1 : i+2;
    for (int j = lo; j <= hi; j++) nb[cnt++] = j;
    if (lev > 0) {
        int c0 = starts[lev-1] + (i - st)*4;
        nb[cnt++] = c0; nb[cnt++] = c0+1; nb[cnt++] = c0+2; nb[cnt++] = c0+3;
    }
    if (lev < 3) nb[cnt++] = starts[lev+1] + (i - st)/4;

    size_t rowb = (size_t)(b*LTOT);
    const float2 qv = *(const float2*)(Q + (rowb + i)*512 + h*64 + lane*2);
    float sc[10];
    #pragma unroll
    for (int t = 0; t < 10; t++) {
        if (t < cnt) {
            float2 kv = *(const float2*)(K + (rowb + nb[t])*512 + h*64 + lane*2);
            float p = qv.x*kv.x + qv.y*kv.y;
            #pragma unroll
            for (int o = 16; o; o >>= 1) p += __shfl_xor_sync(0xffffffffu, p, o);
            sc[t] = p * 0.125f;
        } else sc[t] = -1e30f;
    }
    float mx = -1e30f;
    #pragma unroll
    for (int t = 0; t < 10; t++) mx = fmaxf(mx, sc[t]);
    float ssum = 0.f;
    #pragma unroll
    for (int t = 0; t < 10; t++) {
        sc[t] = (t < cnt) ? expf(sc[t] - mx) : 0.f;
        ssum += sc[t];
    }
    float inv = 1.f / ssum;
    float ax = 0.f, ay = 0.f;
    #pragma unroll
    for (int t = 0; t < 10; t++) {
        if (t < cnt) {
            float2 vv = *(const float2*)(V + (rowb + nb[t])*512 + h*64 + lane*2);
            ax += sc[t]*vv.x; ay += sc[t]*vv.y;
        }
    }
    float vx = ax*inv, vy = ay*inv;
    size_t idx = (rowb + i)*512 + h*64 + lane*2;
    bf16 hx = __float2bfloat16(vx), hy = __float2bfloat16(vy);
    bf16 lx = __float2bfloat16(vx - __bfloat162float(hx));
    bf16 ly = __float2bfloat16(vy - __bfloat162float(hy));
    *(u32*)&Ohi[idx] = (u32)__bfloat16_as_ushort(hx) | ((u32)__bfloat16_as_ushort(hy) << 16);
    *(u32*)&Olo[idx] = (u32)__bfloat16_as_ushort(lx) | ((u32)__bfloat16_as_ushort(ly) << 16);
}

// ---------------- pyramid concat, emits hi/lo ----------------
__global__ void k_pyrcat(const float* __restrict__ c1, const float* __restrict__ c2,
                         const float* __restrict__ c3, bf16* hi, bf16* lo) {
    int idx = blockIdx.x*blockDim.x + threadIdx.x;
    if (idx >= BATCH*336*512) return;
    int d = idx & 511, r = idx >> 9;
    int b = r / 336, p = r % 336;
    float v;
    if (p < 256) v = c1[((size_t)(b*256 + p) << 9) | d];
    else if (p < 320) v = c2[((size_t)(b*64 + p - 256) << 9) | d];
    else v = c3[((size_t)(b*16 + p - 320) << 9) | d];
    wr_hl(hi, lo, idx, v);
}

// ---------------- orchestration ----------------
extern "C" void kernel_launch(void* const* d_in, const int* in_sizes, int n_in,
                              void* d_out, int out_size) {
    const float* x_enc  = (const float*)d_in[0];
    const float* down_W = (const float*)d_in[1];
    const float* down_b = (const float*)d_in[2];
    const float* conv_W = (const float*)d_in[3];
    const float* conv_b = (const float*)d_in[4];
    const float* up_W   = (const float*)d_in[5];
    const float* up_b   = (const float*)d_in[6];
    const float* bc_g   = (const float*)d_in[7];
    const float* bc_b   = (const float*)d_in[8];
    const float* Wq     = (const float*)d_in[9];
    const float* Wk     = (const float*)d_in[10];
    const float* Wv     = (const float*)d_in[11];
    const float* fcW    = (const float*)d_in[12];
    const float* fcb    = (const float*)d_in[13];
    const float* aln_g  = (const float*)d_in[14];
    const float* aln_b  = (const float*)d_in[15];
    const float* W1     = (const float*)d_in[16];
    const float* b1     = (const float*)d_in[17];
    const float* W2     = (const float*)d_in[18];
    const float* b2     = (const float*)d_in[19];
    const float* fln_g  = (const float*)d_in[20];
    const float* fln_b  = (const float*)d_in[21];
    float* out = (float*)d_out;

    float *c1,*c2,*c3,*pyr,*x,*q,*k,*v,*q2,*k2,*v2,*fc,*fc2,*xn,*wc,*sim;
    bf16 *wHI,*wLO,*xhi,*xlo,*xnhi,*xnlo,*oohi,*oolo,*hhi,*hlo;
    bf16 *QH,*QL,*KH,*KL,*VTH,*VTL;
    unsigned char *smk;
    cudaGetSymbolAddress((void**)&c1,  g_c1);
    cudaGetSymbolAddress((void**)&c2,  g_c2);
    cudaGetSymbolAddress((void**)&c3,  g_c3);
    cudaGetSymbolAddress((void**)&pyr, g_pyr);
    cudaGetSymbolAddress((void**)&x,   g_x);
    cudaGetSymbolAddress((void**)&q,   g_q);
    cudaGetSymbolAddress((void**)&k,   g_k);
    cudaGetSymbolAddress((void**)&v,   g_v);
    cudaGetSymbolAddress((void**)&q2,  g_q2);
    cudaGetSymbolAddress((void**)&k2,  g_k2);
    cudaGetSymbolAddress((void**)&v2,  g_v2);
    cudaGetSymbolAddress((void**)&fc,  g_fc);
    cudaGetSymbolAddress((void**)&fc2, g_fc2);
    cudaGetSymbolAddress((void**)&xn,  g_xn);
    cudaGetSymbolAddress((void**)&wc,  g_wc);
    cudaGetSymbolAddress((void**)&sim, g_sim);
    cudaGetSymbolAddress((void**)&wHI, g_wHI);
    cudaGetSymbolAddress((void**)&wLO, g_wLO);
    cudaGetSymbolAddress((void**)&xhi, g_xhi);
    cudaGetSymbolAddress((void**)&xlo, g_xlo);
    cudaGetSymbolAddress((void**)&xnhi,g_xnhi);
    cudaGetSymbolAddress((void**)&xnlo,g_xnlo);
    cudaGetSymbolAddress((void**)&oohi,g_oohi);
    cudaGetSymbolAddress((void**)&oolo,g_oolo);
    cudaGetSymbolAddress((void**)&hhi, g_hhi);
    cudaGetSymbolAddress((void**)&hlo, g_hlo);
    cudaGetSymbolAddress((void**)&QH,  g_QH);
    cudaGetSymbolAddress((void**)&QL,  g_QL);
    cudaGetSymbolAddress((void**)&KH,  g_KH);
    cudaGetSymbolAddress((void**)&KL,  g_KL);
    cudaGetSymbolAddress((void**)&VTH, g_VTH);
    cudaGetSymbolAddress((void**)&VTL, g_VTL);
    cudaGetSymbolAddress((void**)&smk, g_sm);

    cudaFuncSetAttribute(k_mgemm,     cudaFuncAttributeMaxDynamicSharedMemorySize, DSMEM);
    cudaFuncSetAttribute(k_mgemm_qkv, cudaFuncAttributeMaxDynamicSharedMemorySize, DSMEM);
    cudaFuncSetAttribute(k_mgemm_fc,  cudaFuncAttributeMaxDynamicSharedMemorySize, DSMEM);
    cudaFuncSetAttribute(k_mgemm_sim, cudaFuncAttributeMaxDynamicSharedMemorySize, DSMEM);
    cudaFuncSetAttribute(k_fattn,     cudaFuncAttributeMaxDynamicSharedMemorySize, FA_SMEM);

    // ---- upfront weight conversions ----
    k_convw<<<(3*2048*512 + 255)/256, 256>>>(conv_W, wc);
    k_cvtB<<<dim3(16,16), dim3(32,8)>>>(down_W, wHI + WOFF_DOWN, wLO + WOFF_DOWN, 512, 512);
    k_cvtB<<<dim3(16,16), dim3(32,8)>>>(up_W,   wHI + WOFF_UP,   wLO + WOFF_UP,   512, 512);
    k_cvtB_multi<<<dim3(16,64,3), dim3(32,8)>>>(wc, wHI + WOFF_CONV, wLO + WOFF_CONV, 2048, 512);
    k_cvtW_qkv12<<<dim3(16,16,12), dim3(32,8)>>>(Wq, Wk, Wv, wHI + WOFF_QKV, wLO + WOFF_QKV);
    k_cvtB_multi<<<dim3(16,16,4), dim3(32,8)>>>(fcW, wHI + WOFF_FC,   wLO + WOFF_FC,   512, 512);
    k_cvtB_multi<<<dim3(16,16,2), dim3(32,8)>>>(W1,  wHI + WOFF_FFN1, wLO + WOFF_FFN1, 512, 512);
    k_cvtB_multi<<<dim3(16,16,2), dim3(32,8)>>>(W2,  wHI + WOFF_FFN2, wLO + WOFF_FFN2, 512, 512);
    k_cvtA<<<(BATCH*1024*512/4 + 255)/256, 256>>>(x_enc, xhi, xlo, BATCH*1024*512/4);

    // ---- bottleneck ----
    k_mgemm<<<dim3(8,32), 256, DSMEM>>>(xhi, xlo, wHI+WOFF_DOWN, wLO+WOFF_DOWN,
            nullptr, oohi, oolo, down_b, BATCH*1024, 512, 512, 0);
    k_mgemm<<<dim3(8,8), 256, DSMEM>>>(oohi, oolo, wHI+WOFF_CONV, wLO+WOFF_CONV,
            c1, xnhi, xnlo, conv_b, BATCH*256, 512, 2048, 2);
    k_mgemm<<<dim3(8,2), 256, DSMEM>>>(xnhi, xnlo, wHI+WOFF_CONV+1048576, wLO+WOFF_CONV+1048576,
            c2, hhi, hlo, conv_b + 512, BATCH*64, 512, 2048, 2);
    k_mgemm<<<dim3(8,1), 256, DSMEM>>>(hhi, hlo, wHI+WOFF_CONV+2097152, wLO+WOFF_CONV+2097152,
            c3, nullptr, nullptr, conv_b + 1024, BATCH*16, 512, 2048, 2);
    k_pyrcat<<<(BATCH*336*512 + 255)/256, 256>>>(c1, c2, c3, xhi, xlo);
    k_mgemm<<<dim3(8,(BATCH*336 + 127)/128), 256, DSMEM>>>(xhi, xlo, wHI+WOFF_UP, wLO+WOFF_UP,
            pyr, nullptr, nullptr, up_b, BATCH*336, 512, 512, 0);
    k_concat_ln<<<NROWS, 256>>>(x_enc, pyr, bc_g, bc_b, x, xhi, xlo);

    for (int l = 0; l < 2; l++) {
        size_t lo_t = ((size_t)l*2 + 0)*512, lo_s = ((size_t)l*2 + 1)*512;

        // semantic mask
        k_rownorm<<<NROWS, 256>>>(x, xn, xnhi, xnlo);
        k_mgemm_sim<<<dim3(16,8,BATCH), 256, DSMEM>>>(xnhi, xnlo, 0,    1024, 0,       sim);
        k_mgemm_sim<<<dim3(4,2,BATCH),  256, DSMEM>>>(xnhi, xnlo, 1024, 256,  1048576, sim);
        dim3 tg(LTOT, BATCH);
        k_topksel<<<tg, 256>>>(xn, sim, smk);

        // QKV x6 fused
        dim3 qg(8, (NROWS + 127)/128, 6);
        k_mgemm_qkv<<<qg, 256, DSMEM>>>(xhi, xlo,
                wHI + WOFF_QKV + (size_t)l*6*262144, wLO + WOFF_QKV + (size_t)l*6*262144,
                q, k, v, q2, k2, v2, NROWS, 512, 512);

        // temporal branch -> hi/lo
        dim3 sg(LTOT, BATCH);
        k_tattn<<<sg, 256>>>(q, k, v, oohi, oolo);

        // semantic branch: single flash kernel
        {
            long tot = (long)NBH*LPAD*64;
            k_cvt_qk<<<(unsigned)((tot + 255)/256), 256>>>(q2, k2, QH, QL, KH, KL);
            k_cvt_vt<<<dim3(LPAD/32, 2, NBH), dim3(32, 8)>>>(v2, VTH, VTL);
            dim3 fa(11, NBH);
            k_fattn<<<fa, 256, FA_SMEM>>>(QH, QL, KH, KL, VTH, VTL, smk,
                    oohi + (size_t)NROWS*512, oolo + (size_t)NROWS*512);
        }

        // fc x2 fused
        dim3 fg(8, (NROWS + 127)/128, 2);
        k_mgemm_fc<<<fg, 256, DSMEM>>>(oohi, oolo,
                wHI + WOFF_FC + (size_t)l*2*262144, wLO + WOFF_FC + (size_t)l*2*262144,
                fcb, lo_t, lo_s, fc, fc2, NROWS, 512, 512);

        k_lncomb<<<NROWS, 256>>>(fc, fc2, x, xhi, xlo, aln_g, aln_b, lo_t, lo_s);

        // FFN
        size_t fb = (size_t)l*512;
        dim3 ng(8, (NROWS + 127)/128);
        k_mgemm<<<ng, 256, DSMEM>>>(xhi, xlo,
                wHI + WOFF_FFN1 + (size_t)l*262144, wLO + WOFF_FFN1 + (size_t)l*262144,
                nullptr, hhi, hlo, b1 + fb, NROWS, 512, 512, 1);
        k_mgemm<<<ng, 256, DSMEM>>>(hhi, hlo,
                wHI + WOFF_FFN2 + (size_t)l*262144, wLO + WOFF_FFN2 + (size_t)l*262144,
                fc, nullptr, nullptr, b2 + fb, NROWS, 512, 512, 0);
        if (l == 0)
            k_add_ln<<<NROWS, 256>>>(fc, x, fln_g + fb, fln_b + fb, x, xhi, xlo, 1e-6f);
        else
            k_add_ln<<<NROWS, 256>>>(fc, x, fln_g + fb, fln_b + fb, out, nullptr, nullptr, 1e-6f);
    }
}

// round 15
// speedup vs baseline: 1.1365x; 1.1365x over previous
#include <cuda_runtime.h>
#include <cuda_bf16.h>
#include <math.h>
#include <stdint.h>

#define LTOT   1360
#define BATCH  4
#define NROWS  (BATCH*LTOT)          // 5440
#define L2SZ   ((size_t)LTOT*LTOT)
#define SIMB   (1048576 + 65536)
#define LPAD   1408
#define NBH    (BATCH*8)
#define NJT    22

// weight arena element offsets
#define WOFF_DOWN 0
#define WOFF_UP   262144
#define WOFF_CONV 524288
#define WOFF_QKV  3670016
#define WOFF_FC   6815744
#define WOFF_FFN1 7864320
#define WOFF_FFN2 8388608
#define WTOT      8912896

typedef __nv_bfloat16 bf16;
typedef unsigned int u32;

// ---------------- static device scratch ----------------
__device__ float g_c1[BATCH*256*512];
__device__ float g_c2[BATCH*64*512];
__device__ float g_c3[BATCH*16*512];
__device__ float g_pyr[BATCH*336*512];
__device__ float g_x[NROWS*512];
__device__ float g_q[NROWS*512];
__device__ float g_k[NROWS*512];
__device__ float g_v[NROWS*512];
__device__ float g_v2[NROWS*512];
__device__ float g_fc[NROWS*512];
__device__ float g_fc2[NROWS*512];
__device__ float g_xn[NROWS*512];
__device__ float g_wc[3*2048*512];
__device__ float g_sim[(size_t)BATCH*SIMB];
__device__ unsigned char g_sm[(size_t)BATCH*LTOT*LTOT];
// bf16 hi/lo operand buffers
__device__ bf16 g_wHI[WTOT];
__device__ bf16 g_wLO[WTOT];
__device__ bf16 g_xhi[NROWS*512];
__device__ bf16 g_xlo[NROWS*512];
__device__ bf16 g_xnhi[NROWS*512];
__device__ bf16 g_xnlo[NROWS*512];
__device__ bf16 g_oohi[2*NROWS*512];
__device__ bf16 g_oolo[2*NROWS*512];
__device__ bf16 g_hhi[NROWS*512];
__device__ bf16 g_hlo[NROWS*512];
// attention buffers (padded rows [LTOT,LPAD) stay zero from static init — never written)
__device__ bf16 g_QH[(size_t)NBH*LPAD*64];
__device__ bf16 g_QL[(size_t)NBH*LPAD*64];
__device__ bf16 g_KH[(size_t)NBH*LPAD*64];
__device__ bf16 g_KL[(size_t)NBH*LPAD*64];
__device__ bf16 g_VTH[(size_t)NBH*64*LPAD];
__device__ bf16 g_VTL[(size_t)NBH*64*LPAD];
__device__ bf16 g_PH[(size_t)NBH*LTOT*LPAD];
__device__ bf16 g_PL[(size_t)NBH*LTOT*LPAD];
__device__ float g_psum[(size_t)NBH*LTOT*NJT];
__device__ float g_rsum[(size_t)NBH*LTOT];

__device__ __forceinline__ void wr_hl(bf16* hi, bf16* lo, size_t idx, float v) {
    bf16 h = __float2bfloat16(v);
    hi[idx] = h;
    lo[idx] = __float2bfloat16(v - __bfloat162float(h));
}

// ---------------- fp32 -> bf16 hi/lo (flat) ----------------
__global__ void k_cvtA(const float* __restrict__ s, bf16* __restrict__ hi,
                       bf16* __restrict__ lo, int n4) {
    int i = blockIdx.x*blockDim.x + threadIdx.x;
    if (i >= n4) return;
    float4 v = ((const float4*)s)[i];
    bf16 h0=__float2bfloat16(v.x), h1=__float2bfloat16(v.y),
         h2=__float2bfloat16(v.z), h3=__float2bfloat16(v.w);
    bf16 l0=__float2bfloat16(v.x-__bfloat162float(h0)),
         l1=__float2bfloat16(v.y-__bfloat162float(h1)),
         l2=__float2bfloat16(v.z-__bfloat162float(h2)),
         l3=__float2bfloat16(v.w-__bfloat162float(h3));
    uint2 hp = make_uint2((u32)__bfloat16_as_ushort(h0) | ((u32)__bfloat16_as_ushort(h1)<<16),
                          (u32)__bfloat16_as_ushort(h2) | ((u32)__bfloat16_as_ushort(h3)<<16));
    uint2 lp = make_uint2((u32)__bfloat16_as_ushort(l0) | ((u32)__bfloat16_as_ushort(l1)<<16),
                          (u32)__bfloat16_as_ushort(l2) | ((u32)__bfloat16_as_ushort(l3)<<16));
    ((uint2*)hi)[i] = hp;
    ((uint2*)lo)[i] = lp;
}

// ---------------- fp32 [K][N] -> bf16 hi/lo transposed [N][K] ----------------
__device__ __forceinline__ void cvtB_body(const float* __restrict__ src,
        bf16* __restrict__ hi, bf16* __restrict__ lo, int K, int N) {
    __shared__ float t[32][33];
    int tx = threadIdx.x, ty = threadIdx.y;
    int n0 = blockIdx.x*32, k0 = blockIdx.y*32;
    #pragma unroll
    for (int i = 0; i < 4; i++)
        t[ty + i*8][tx] = src[(size_t)(k0 + ty + i*8)*N + n0 + tx];
    __syncthreads();
    #pragma unroll
    for (int i = 0; i < 4; i++) {
        float v = t[tx][ty + i*8];
        int n = n0 + ty + i*8, kk = k0 + tx;
        wr_hl(hi, lo, (size_t)n*K + kk, v);
    }
}
__global__ void k_cvtB(const float* __restrict__ src, bf16* hi, bf16* lo, int K, int N) {
    cvtB_body(src, hi, lo, K, N);
}
__global__ void k_cvtB_multi(const float* __restrict__ src, bf16* hi, bf16* lo,
                             int K, int N) {
    size_t off = (size_t)blockIdx.z*K*N;
    cvtB_body(src + off, hi + off, lo + off, K, N);
}
__global__ void k_cvtW_qkv12(const float* __restrict__ Wq, const float* __restrict__ Wk,
                             const float* __restrict__ Wv, bf16* hi, bf16* lo) {
    int z = blockIdx.z;
    int l = z/6, rem = z%6, s = rem/3, c = rem%3;
    const float* base = ((c==0)?Wq:(c==1)?Wk:Wv) + ((size_t)(l*2+s))*262144;
    cvtB_body(base, hi + (size_t)z*262144, lo + (size_t)z*262144, 512, 512);
}

// ---------------- bf16x3 MMA GEMM with cp.async double-buffer ----------------
__device__ __forceinline__ void mma16816(float* d, const u32* a, const u32* b) {
    asm volatile(
        "mma.sync.aligned.m16n8k16.row.col.f32.bf16.bf16.f32 "
        "{%0,%1,%2,%3}, {%4,%5,%6,%7}, {%8,%9}, {%0,%1,%2,%3};"
        : "+f"(d[0]), "+f"(d[1]), "+f"(d[2]), "+f"(d[3])
        : "r"(a[0]), "r"(a[1]), "r"(a[2]), "r"(a[3]), "r"(b[0]), "r"(b[1]));
}
#define AP 40
#define ABUF (128*AP)
#define BBUF (64*AP)
#define BUFELEM (2*ABUF + 2*BBUF)
#define DSMEM (2*BUFELEM*2)

__device__ __forceinline__ u32 sm32(const void* p) {
    return (u32)__cvta_generic_to_shared(p);
}
__device__ __forceinline__ void cp16(u32 dst, const void* src, int bytes) {
    asm volatile("cp.async.ca.shared.global [%0], [%1], 16, %2;"
                 :: "r"(dst), "l"(src), "r"(bytes));
}

#define MG_LOADC(kc, bsel)                                                     \
    {                                                                          \
        bf16* base = dsm + (bsel)*BUFELEM;                                     \
        _Pragma("unroll")                                                      \
        for (int s = 0; s < 2; s++) {                                          \
            int slot = s*256 + tid;                                            \
            int r = slot >> 2, k16 = (slot & 3) << 3;                          \
            int gr = row0 + r;                                                 \
            int ok = (gr < M) ? 16 : 0;                                        \
            size_t go = (size_t)(gr < M ? gr : 0)*K + (kc) + k16;              \
            cp16(sm32(base + r*AP + k16), Ahi + go, ok);                       \
            cp16(sm32(base + ABUF + r*AP + k16), Alo + go, ok);                \
        }                                                                      \
        {                                                                      \
            int r = tid >> 2, k16 = (tid & 3) << 3;                            \
            size_t go = (size_t)(col0 + r)*K + (kc) + k16;                     \
            cp16(sm32(base + 2*ABUF + r*AP + k16), Bhi + go, 16);              \
            cp16(sm32(base + 2*ABUF + BBUF + r*AP + k16), Blo + go, 16);       \
        }                                                                      \
        asm volatile("cp.async.commit_group;" ::: "memory");                   \
    }

#define MG_MAINLOOP()                                                          \
    MG_LOADC(0, 0);                                                            \
    int buf = 0;                                                               \
    for (int kc = 0; kc < K; kc += 32) {                                       \
        bool more = (kc + 32) < K;                                             \
        if (more) {                                                            \
            MG_LOADC(kc + 32, buf ^ 1);                                        \
            asm volatile("cp.async.wait_group 1;" ::: "memory");               \
        } else {                                                               \
            asm volatile("cp.async.wait_group 0;" ::: "memory");               \
        }                                                                      \
        __syncthreads();                                                       \
        const bf16* As0 = dsm + buf*BUFELEM;                                   \
        const bf16* As1 = As0 + ABUF;                                          \
        const bf16* Bs0 = As0 + 2*ABUF;                                        \
        const bf16* Bs1 = Bs0 + BBUF;                                          \
        _Pragma("unroll")                                                      \
        for (int ks = 0; ks < 32; ks += 16) {                                  \
            u32 ah[2][4], al[2][4], bh[4][2], bl[4][2];                        \
            _Pragma("unroll")                                                  \
            for (int mt = 0; mt < 2; mt++) {                                   \
                int ar = (wm*32 + mt*16 + g)*AP + ks + qp*2;                   \
                int ar8 = ar + 8*AP;                                           \
                ah[mt][0] = *(const u32*)&As0[ar];                             \
                ah[mt][1] = *(const u32*)&As0[ar8];                            \
                ah[mt][2] = *(const u32*)&As0[ar + 8];                         \
                ah[mt][3] = *(const u32*)&As0[ar8 + 8];                        \
                al[mt][0] = *(const u32*)&As1[ar];                             \
                al[mt][1] = *(const u32*)&As1[ar8];                            \
                al[mt][2] = *(const u32*)&As1[ar + 8];                         \
                al[mt][3] = *(const u32*)&As1[ar8 + 8];                        \
            }                                                                  \
            _Pragma("unroll")                                                  \
            for (int nt = 0; nt < 4; nt++) {                                   \
                int br = (wn*32 + nt*8 + g)*AP + ks + qp*2;                    \
                bh[nt][0] = *(const u32*)&Bs0[br];                             \
                bh[nt][1] = *(const u32*)&Bs0[br + 8];                         \
                bl[nt][0] = *(const u32*)&Bs1[br];                             \
                bl[nt][1] = *(const u32*)&Bs1[br + 8];                         \
            }                                                                  \
            _Pragma("unroll")                                                  \
            for (int mt = 0; mt < 2; mt++)                                     \
                _Pragma("unroll")                                              \
                for (int nt = 0; nt < 4; nt++) {                               \
                    mma16816(acc[mt][nt], ah[mt], bh[nt]);                     \
                    mma16816(acc[mt][nt], ah[mt], bl[nt]);                     \
                    mma16816(acc[mt][nt], al[mt], bh[nt]);                     \
                }                                                              \
        }                                                                      \
        __syncthreads();                                                       \
        buf ^= 1;                                                              \
    }

// mode: 0 none, 1 relu, 2 scale+elu. C/Chi may be null; rmul scales rows.
// hsplit: Chi/Clo indexed head-split padded [(b*8+h)*LPAD + i]*64 + d.
__device__ void mg_body(const bf16* __restrict__ Ahi, const bf16* __restrict__ Alo,
                        const bf16* __restrict__ Bhi, const bf16* __restrict__ Blo,
                        float* __restrict__ C, bf16* __restrict__ Chi,
                        bf16* __restrict__ Clo, const float* __restrict__ bias,
                        const float* __restrict__ rmul,
                        int M, int N, int K, int mode, int ldc, int hsplit) {
    extern __shared__ bf16 dsm[];
    int tid = threadIdx.x, wid = tid >> 5, lane = tid & 31;
    int wm = wid >> 1, wn = wid & 1, g = lane >> 2, qp = lane & 3;
    int row0 = blockIdx.y << 7, col0 = blockIdx.x << 6;
    float acc[2][4][4] = {};
    MG_MAINLOOP();
    #pragma unroll
    for (int mt = 0; mt < 2; mt++) {
        #pragma unroll
        for (int half = 0; half < 2; half++) {
            int r = row0 + wm*32 + mt*16 + g + half*8;
            if (r >= M) continue;
            float rmv = rmul ? rmul[r] : 1.f;
            int bq = 0, iq = 0;
            if (hsplit) { bq = r / LTOT; iq = r - bq*LTOT; }
            #pragma unroll
            for (int nt = 0; nt < 4; nt++) {
                int cl = col0 + wn*32 + nt*8 + qp*2;
                float v0 = acc[mt][nt][half*2 + 0], v1 = acc[mt][nt][half*2 + 1];
                if (rmul) { v0 *= rmv; v1 *= rmv; }
                if (bias) { v0 += bias[cl]; v1 += bias[cl + 1]; }
                if (mode == 1) { v0 = fmaxf(v0, 0.f); v1 = fmaxf(v1, 0.f); }
                else if (mode == 2) {
                    v0 *= 0.9999950000374997f; if (v0 <= 0.f) v0 = expm1f(v0);
                    v1 *= 0.9999950000374997f; if (v1 <= 0.f) v1 = expm1f(v1);
                }
                size_t ci;
                if (hsplit) {
                    int hh = cl >> 6, dd = cl & 63;
                    ci = (((size_t)(bq*8 + hh))*LPAD + iq)*64 + dd;
                } else {
                    ci = (size_t)r*ldc + cl;
                }
                if (C) *(float2*)&C[ci] = make_float2(v0, v1);
                if (Chi) {
                    bf16 h0 = __float2bfloat16(v0), h1 = __float2bfloat16(v1);
                    bf16 l0 = __float2bfloat16(v0 - __bfloat162float(h0));
                    bf16 l1 = __float2bfloat16(v1 - __bfloat162float(h1));
                    *(u32*)&Chi[ci] = (u32)__bfloat16_as_ushort(h0) |
                                      ((u32)__bfloat16_as_ushort(h1) << 16);
                    *(u32*)&Clo[ci] = (u32)__bfloat16_as_ushort(l0) |
                                      ((u32)__bfloat16_as_ushort(l1) << 16);
                }
            }
        }
    }
}

__global__ void __launch_bounds__(256) k_mgemm(
        const bf16* Ahi, const bf16* Alo, const bf16* Bhi, const bf16* Blo,
        float* C, bf16* Chi, bf16* Clo, const float* bias,
        int M, int N, int K, int mode) {
    mg_body(Ahi, Alo, Bhi, Blo, C, Chi, Clo, bias, nullptr, M, N, K, mode, N, 0);
}
// QKV: z 0-2 -> t-branch fp32 q/k/v; z=3 -> QH/QL head-split; z=4 -> KH/KL; z=5 -> v2 fp32
__global__ void __launch_bounds__(256) k_mgemm_qkv(
        const bf16* Ahi, const bf16* Alo, const bf16* Bhi, const bf16* Blo,
        float* q, float* k, float* v, float* v2,
        bf16* QH, bf16* QL, bf16* KH, bf16* KL,
        int M, int N, int K) {
    int z = blockIdx.z;
    size_t bo = (size_t)z*262144;
    if (z == 3 || z == 4) {
        bf16* H = (z == 3) ? QH : KH;
        bf16* L = (z == 3) ? QL : KL;
        mg_body(Ahi, Alo, Bhi + bo, Blo + bo, nullptr, H, L, nullptr, nullptr,
                M, N, K, 0, N, 1);
    } else {
        float* C = (z==0)?q:(z==1)?k:(z==2)?v:v2;
        mg_body(Ahi, Alo, Bhi + bo, Blo + bo, C, nullptr, nullptr, nullptr, nullptr,
                M, N, K, 0, N, 0);
    }
}
__global__ void __launch_bounds__(256) k_mgemm_fc(
        const bf16* Ahi, const bf16* Alo, const bf16* Bhi, const bf16* Blo,
        const float* fcb, size_t lo_t, size_t lo_s,
        float* ft, float* fs, int M, int N, int K) {
    int z = blockIdx.z;
    size_t ao = (size_t)z*NROWS*512, bo = (size_t)z*262144;
    mg_body(Ahi + ao, Alo + ao, Bhi + bo, Blo + bo, z ? fs : ft, nullptr, nullptr,
            fcb + (z ? lo_s : lo_t), nullptr, M, N, K, 0, N, 0);
}
__global__ void __launch_bounds__(256) k_mgemm_sim(
        const bf16* Ahi, const bf16* Alo, int startRow, int n, size_t lvloff,
        float* simbuf) {
    int b = blockIdx.z;
    size_t ao = ((size_t)(b*LTOT + startRow))*512;
    float* C = simbuf + (size_t)b*SIMB + lvloff;
    mg_body(Ahi + ao, Alo + ao, Ahi + ao, Alo + ao, C, nullptr, nullptr, nullptr,
            nullptr, n, n, 512, 0, n, 0);
}
__global__ void __launch_bounds__(256) k_mgemm_att_pv(
        const bf16* PH, const bf16* PL, const bf16* VTH, const bf16* VTL,
        const float* rsum, bf16* Ohi, bf16* Olo) {
    int bh = blockIdx.z, b = bh >> 3, h = bh & 7;
    size_t po = (size_t)bh*LTOT*LPAD, vo = (size_t)bh*64*LPAD;
    size_t co = ((size_t)b*LTOT)*512 + h*64;
    mg_body(PH + po, PL + po, VTH + vo, VTL + vo,
            nullptr, Ohi + co, Olo + co, nullptr, rsum + (size_t)bh*LTOT,
            LTOT, 64, LPAD, 0, 512, 0);
}

// ---- fused S = QK^T with mask+exp epilogue + deterministic row partials ----
__global__ void __launch_bounds__(256) k_att_s(
        const bf16* __restrict__ QHg, const bf16* __restrict__ QLg,
        const bf16* __restrict__ KHg, const bf16* __restrict__ KLg,
        const unsigned char* __restrict__ smask,
        bf16* __restrict__ PH, bf16* __restrict__ PL,
        float* __restrict__ psum) {
    extern __shared__ bf16 dsm[];
    __shared__ float psm[128][2];
    int bh = blockIdx.z, b = bh >> 3;
    const bf16* Ahi = QHg + (size_t)bh*LPAD*64;
    const bf16* Alo = QLg + (size_t)bh*LPAD*64;
    const bf16* Bhi = KHg + (size_t)bh*LPAD*64;
    const bf16* Blo = KLg + (size_t)bh*LPAD*64;
    int tid = threadIdx.x, wid = tid >> 5, lane = tid & 31;
    int wm = wid >> 1, wn = wid & 1, g = lane >> 2, qp = lane & 3;
    int row0 = blockIdx.y << 7, col0 = blockIdx.x << 6;
    const int M = LTOT, K = 64;
    float acc[2][4][4] = {};
    MG_MAINLOOP();
    float rp[2][2];
    #pragma unroll
    for (int mt = 0; mt < 2; mt++) {
        #pragma unroll
        for (int half = 0; half < 2; half++) {
            int r = row0 + wm*32 + mt*16 + g + half*8;
            bool rok = (r < M);
            const unsigned char* mrow = smask + ((size_t)b*LTOT + (rok ? r : 0))*LTOT;
            float rs = 0.f;
            #pragma unroll
            for (int nt = 0; nt < 4; nt++) {
                int cl = col0 + wn*32 + nt*8 + qp*2;
                float e0 = 0.f, e1 = 0.f;
                if (rok) {
                    if (cl < LTOT && !mrow[cl])
                        e0 = __expf(acc[mt][nt][half*2 + 0]*0.125f);
                    if (cl + 1 < LTOT && !mrow[cl + 1])
                        e1 = __expf(acc[mt][nt][half*2 + 1]*0.125f);
                    size_t ci = ((size_t)bh*LTOT + r)*LPAD + cl;
                    bf16 h0 = __float2bfloat16(e0), h1 = __float2bfloat16(e1);
                    bf16 l0 = __float2bfloat16(e0 - __bfloat162float(h0));
                    bf16 l1 = __float2bfloat16(e1 - __bfloat162float(h1));
                    *(u32*)&PH[ci] = (u32)__bfloat16_as_ushort(h0) |
                                     ((u32)__bfloat16_as_ushort(h1) << 16);
                    *(u32*)&PL[ci] = (u32)__bfloat16_as_ushort(l0) |
                                     ((u32)__bfloat16_as_ushort(l1) << 16);
                }
                rs += e0 + e1;
            }
            rp[mt][half] = rs;
        }
    }
    #pragma unroll
    for (int mt = 0; mt < 2; mt++)
        #pragma unroll
        for (int half = 0; half < 2; half++) {
            float v = rp[mt][half];
            v += __shfl_xor_sync(0xffffffffu, v, 1);
            v += __shfl_xor_sync(0xffffffffu, v, 2);
            if (qp == 0) psm[wm*32 + mt*16 + half*8 + g][wn] = v;
        }
    __syncthreads();
    if (tid < 128) {
        int r = row0 + tid;
        if (r < M)
            psum[((size_t)bh*LTOT + r)*NJT + blockIdx.x] = psm[tid][0] + psm[tid][1];
    }
}

__global__ void k_rsumfin(const float* __restrict__ psum, float* __restrict__ rsum) {
    int i = blockIdx.x*256 + threadIdx.x;
    if (i >= NBH*LTOT) return;
    const float* p = psum + (size_t)i*NJT;
    float s = 0.f;
    #pragma unroll
    for (int j = 0; j < NJT; j++) s += p[j];
    rsum[i] = 1.f / s;
}

// ---------------- V transpose conversion ----------------
__global__ void k_cvt_vt(const float* __restrict__ v2, bf16* VTH, bf16* VTL) {
    __shared__ float t[32][33];
    int bh = blockIdx.z, b = bh >> 3, h = bh & 7;
    int j0 = blockIdx.x*32, d0 = blockIdx.y*32;
    int tx = threadIdx.x, ty = threadIdx.y;
    #pragma unroll
    for (int i = 0; i < 4; i++) {
        int j = j0 + ty + i*8;
        t[ty + i*8][tx] = (j < LTOT)
            ? v2[((size_t)(b*LTOT + j))*512 + h*64 + d0 + tx] : 0.f;
    }
    __syncthreads();
    #pragma unroll
    for (int i = 0; i < 4; i++) {
        int d = d0 + ty + i*8, j = j0 + tx;
        wr_hl(VTH, VTL, ((size_t)bh*64 + d)*LPAD + j, t[tx][ty + i*8]);
    }
}

// ---------------- reductions ----------------
__device__ __forceinline__ float block_sum256(float v) {
    __shared__ float red[8];
    int lane = threadIdx.x & 31, w = threadIdx.x >> 5;
    #pragma unroll
    for (int o = 16; o; o >>= 1) v += __shfl_xor_sync(0xffffffffu, v, o);
    if (lane == 0) red[w] = v;
    __syncthreads();
    if (w == 0) {
        float t = (lane < 8) ? red[lane] : 0.f;
        #pragma unroll
        for (int o = 4; o; o >>= 1) t += __shfl_xor_sync(0xffffffffu, t, o);
        if (lane == 0) red[0] = t;
    }
    __syncthreads();
    float r = red[0];
    __syncthreads();
    return r;
}

// ---------------- conv weight re-layout ----------------
__global__ void k_convw(const float* __restrict__ w, float* __restrict__ wm) {
    int idx = blockIdx.x*blockDim.x + threadIdx.x;
    if (idx >= 3*2048*512) return;
    int l  = idx / (2048*512);
    int r  = idx - l*2048*512;
    int kk = r >> 9, co = r & 511;
    int t  = kk >> 9, ci = kk & 511;
    wm[idx] = w[(((size_t)(l*512 + co))*512 + ci)*4 + t];
}

// ---------------- concat + LN(1e-5), emits hi/lo ----------------
__global__ void __launch_bounds__(256) k_concat_ln(
        const float* __restrict__ xe, const float* __restrict__ pyr,
        const float* __restrict__ g, const float* __restrict__ bt,
        float* __restrict__ out, bf16* ohi, bf16* olo) {
    int row = blockIdx.x;
    int b = row / LTOT, i = row % LTOT;
    const float* src = (i < 1024) ? xe + ((size_t)(b*1024 + i))*512
                                  : pyr + ((size_t)(b*336 + (i - 1024)))*512;
    int t = threadIdx.x;
    float v0 = src[t], v1 = src[t + 256];
    float mu = block_sum256(v0 + v1) * (1.f/512.f);
    float d0 = v0 - mu, d1 = v1 - mu;
    float var = block_sum256(d0*d0 + d1*d1) * (1.f/512.f);
    float rs = rsqrtf(var + 1e-5f);
    float r0 = d0*rs*g[t]       + bt[t];
    float r1 = d1*rs*g[t + 256] + bt[t + 256];
    size_t base = (size_t)row*512;
    out[base + t] = r0; out[base + t + 256] = r1;
    wr_hl(ohi, olo, base + t, r0);
    wr_hl(ohi, olo, base + t + 256, r1);
}

// ---------------- (a+res) -> LN, optional hi/lo ----------------
__global__ void __launch_bounds__(256) k_add_ln(
        const float* __restrict__ a, const float* __restrict__ res,
        const float* __restrict__ g, const float* __restrict__ bt,
        float* __restrict__ out, bf16* ohi, bf16* olo, float eps) {
    int row = blockIdx.x, t = threadIdx.x;
    const float* pa = a + (size_t)row*512;
    const float* pr = res + (size_t)row*512;
    float v0 = pa[t] + pr[t], v1 = pa[t + 256] + pr[t + 256];
    float mu = block_sum256(v0 + v1) * (1.f/512.f);
    float d0 = v0 - mu, d1 = v1 - mu;
    float var = block_sum256(d0*d0 + d1*d1) * (1.f/512.f);
    float rs = rsqrtf(var + eps);
    float r0 = d0*rs*g[t]       + bt[t];
    float r1 = d1*rs*g[t + 256] + bt[t + 256];
    size_t base = (size_t)row*512;
    out[base + t] = r0; out[base + t + 256] = r1;
    if (ohi) {
        wr_hl(ohi, olo, base + t, r0);
        wr_hl(ohi, olo, base + t + 256, r1);
    }
}

// ---------------- fused dual-LN + combine, emits hi/lo ----------------
__global__ void __launch_bounds__(256) k_lncomb(
        const float* __restrict__ fc, const float* __restrict__ fc2,
        float* __restrict__ x, bf16* xhi, bf16* xlo,
        const float* __restrict__ g, const float* __restrict__ bt,
        size_t lo_t, size_t lo_s) {
    int row = blockIdx.x, t = threadIdx.x;
    const float* pa = fc + (size_t)row*512;
    const float* pb = fc2 + (size_t)row*512;
    float* px = x + (size_t)row*512;
    float x0 = px[t], x1 = px[t + 256];
    float a0 = pa[t] + x0, a1 = pa[t + 256] + x1;
    float b0 = pb[t] + x0, b1 = pb[t + 256] + x1;
    float mu = block_sum256(a0 + a1) * (1.f/512.f);
    a0 -= mu; a1 -= mu;
    float var = block_sum256(a0*a0 + a1*a1) * (1.f/512.f);
    float rs = rsqrtf(var + 1e-6f);
    float t0 = a0*rs*g[lo_t + t]       + bt[lo_t + t];
    float t1 = a1*rs*g[lo_t + t + 256] + bt[lo_t + t + 256];
    mu = block_sum256(b0 + b1) * (1.f/512.f);
    b0 -= mu; b1 -= mu;
    var = block_sum256(b0*b0 + b1*b1) * (1.f/512.f);
    rs = rsqrtf(var + 1e-6f);
    float s0 = b0*rs*g[lo_s + t]       + bt[lo_s + t];
    float s1 = b1*rs*g[lo_s + t + 256] + bt[lo_s + t + 256];
    float r0 = (t0 + s0 + x0) * (1.f/3.f);
    float r1 = (t1 + s1 + x1) * (1.f/3.f);
    px[t] = r0; px[t + 256] = r1;
    size_t base = (size_t)row*512;
    wr_hl(xhi, xlo, base + t, r0);
    wr_hl(xhi, xlo, base + t + 256, r1);
}

// ---------------- row L2 normalize, emits hi/lo ----------------
__global__ void __launch_bounds__(256) k_rownorm(
        const float* __restrict__ x, float* __restrict__ xn,
        bf16* nhi, bf16* nlo) {
    int row = blockIdx.x, t = threadIdx.x;
    const float* p = x + (size_t)row*512;
    float v0 = p[t], v1 = p[t + 256];
    float ss = block_sum256(v0*v0 + v1*v1);
    float inv = 1.f / fmaxf(sqrtf(ss), 1e-8f);
    float r0 = v0*inv, r1 = v1*inv;
    size_t base = (size_t)row*512;
    xn[base + t] = r0; xn[base + t + 256] = r1;
    wr_hl(nhi, nlo, base + t, r0);
    wr_hl(nhi, nlo, base + t + 256, r1);
}

// ---------------- top-k select ----------------
__global__ void __launch_bounds__(256) k_topksel(
        const float* __restrict__ xn, const float* __restrict__ simbuf,
        unsigned char* __restrict__ smask) {
    int i = blockIdx.x, b = blockIdx.y, tid = threadIdx.x;
    const int starts[4] = {0,1024,1280,1344};
    const int sizes[4]  = {1024,256,64,16};
    int lev = (i<1024)?0:(i<1280)?1:(i<1344)?2:3;
    int st = starts[lev], n = sizes[lev];
    int kk = n < 32 ? n : 32;
    __shared__ float sims[1024];
    __shared__ float qrow[512];
    __shared__ float wv[8]; __shared__ int wi[8];
    unsigned char* mrow = smask + ((size_t)b*LTOT + i)*LTOT + st;
    for (int j = tid; j < n; j += 256) mrow[j] = 0;
    if (lev <= 1) {
        size_t lvloff = (lev == 0) ? 0 : 1048576;
        const float* srow = simbuf + (size_t)b*SIMB + lvloff + (size_t)(i - st)*n;
        for (int j = tid; j < n; j += 256) sims[j] = srow[j];
        __syncthreads();
    } else {
        const float* xb = xn + (size_t)b*LTOT*512;
        for (int d = tid; d < 512; d += 256) qrow[d] = xb[(size_t)i*512 + d];
        __syncthreads();
        int w = tid >> 5, lane = tid & 31;
        for (int j = w; j < n; j += 8) {
            const float* rj = xb + (size_t)(st + j)*512;
            float p = 0.f;
            #pragma unroll 4
            for (int d = lane; d < 512; d += 32) p += qrow[d]*rj[d];
            #pragma unroll
            for (int o = 16; o; o >>= 1) p += __shfl_xor_sync(0xffffffffu, p, o);
            if (lane == 0) sims[j] = p;
        }
        __syncthreads();
    }
    int w = tid >> 5, lane = tid & 31;
    for (int it = 0; it < kk; it++) {
        float bv = -3.f; int bi = n;
        for (int j = tid; j < n; j += 256) {
            float v = sims[j];
            if (v > bv) { bv = v; bi = j; }
        }
        #pragma unroll
        for (int o = 16; o; o >>= 1) {
            float ov = __shfl_xor_sync(0xffffffffu, bv, o);
            int   oi = __shfl_xor_sync(0xffffffffu, bi, o);
            if (ov > bv || (ov == bv && oi < bi)) { bv = ov; bi = oi; }
        }
        if (lane == 0) { wv[w] = bv; wi[w] = bi; }
        __syncthreads();
        if (tid == 0) {
            float fv = wv[0]; int fi = wi[0];
            #pragma unroll
            for (int z = 1; z < 8; z++)
                if (wv[z] > fv || (wv[z] == fv && wi[z] < fi)) { fv = wv[z]; fi = wi[z]; }
            mrow[fi] = 1;
            sims[fi] = -3.f;
        }
        __syncthreads();
    }
}

// ---------------- SPARSE temporal attention, emits hi/lo ----------------
__global__ void __launch_bounds__(256) k_tattn(
        const float* __restrict__ Q, const float* __restrict__ K,
        const float* __restrict__ V, bf16* __restrict__ Ohi, bf16* __restrict__ Olo) {
    int i = blockIdx.x, b = blockIdx.y;
    int h = threadIdx.x >> 5, lane = threadIdx.x & 31;
    const int starts[4] = {0,1024,1280,1344};
    const int sizes[4]  = {1024,256,64,16};
    int lev = (i<1024)?0:(i<1280)?1:(i<1344)?2:3;
    int st = starts[lev], n = sizes[lev];
    int nb[10]; int cnt = 0;
    int lo = (i-2 < st) ? st : i-2;
    int hi = (i+2 > st+n-1) ? st+n-1 : i+2;
    for (int j = lo; j <= hi; j++) nb[cnt++] = j;
    if (lev > 0) {
        int c0 = starts[lev-1] + (i - st)*4;
        nb[cnt++] = c0; nb[cnt++] = c0+1; nb[cnt++] = c0+2; nb[cnt++] = c0+3;
    }
    if (lev < 3) nb[cnt++] = starts[lev+1] + (i - st)/4;

    size_t rowb = (size_t)(b*LTOT);
    const float2 qv = *(const float2*)(Q + (rowb + i)*512 + h*64 + lane*2);
    float sc[10];
    #pragma unroll
    for (int t = 0; t < 10; t++) {
        if (t < cnt) {
            float2 kv = *(const float2*)(K + (rowb + nb[t])*512 + h*64 + lane*2);
            float p = qv.x*kv.x + qv.y*kv.y;
            #pragma unroll
            for (int o = 16; o; o >>= 1) p += __shfl_xor_sync(0xffffffffu, p, o);
            sc[t] = p * 0.125f;
        } else sc[t] = -1e30f;
    }
    float mx = -1e30f;
    #pragma unroll
    for (int t = 0; t < 10; t++) mx = fmaxf(mx, sc[t]);
    float ssum = 0.f;
    #pragma unroll
    for (int t = 0; t < 10; t++) {
        sc[t] = (t < cnt) ? __expf(sc[t] - mx) : 0.f;
        ssum += sc[t];
    }
    float inv = 1.f / ssum;
    float ax = 0.f, ay = 0.f;
    #pragma unroll
    for (int t = 0; t < 10; t++) {
        if (t < cnt) {
            float2 vv = *(const float2*)(V + (rowb + nb[t])*512 + h*64 + lane*2);
            ax += sc[t]*vv.x; ay += sc[t]*vv.y;
        }
    }
    float vx = ax*inv, vy = ay*inv;
    size_t idx = (rowb + i)*512 + h*64 + lane*2;
    bf16 hx = __float2bfloat16(vx), hy = __float2bfloat16(vy);
    bf16 lx = __float2bfloat16(vx - __bfloat162float(hx));
    bf16 ly = __float2bfloat16(vy - __bfloat162float(hy));
    *(u32*)&Ohi[idx] = (u32)__bfloat16_as_ushort(hx) | ((u32)__bfloat16_as_ushort(hy) << 16);
    *(u32*)&Olo[idx] = (u32)__bfloat16_as_ushort(lx) | ((u32)__bfloat16_as_ushort(ly) << 16);
}

// ---------------- pyramid concat, emits hi/lo ----------------
__global__ void k_pyrcat(const float* __restrict__ c1, const float* __restrict__ c2,
                         const float* __restrict__ c3, bf16* hi, bf16* lo) {
    int idx = blockIdx.x*blockDim.x + threadIdx.x;
    if (idx >= BATCH*336*512) return;
    int d = idx & 511, r = idx >> 9;
    int b = r / 336, p = r % 336;
    float v;
    if (p < 256) v = c1[((size_t)(b*256 + p) << 9) | d];
    else if (p < 320) v = c2[((size_t)(b*64 + p - 256) << 9) | d];
    else v = c3[((size_t)(b*16 + p - 320) << 9) | d];
    wr_hl(hi, lo, idx, v);
}

// ---------------- orchestration ----------------
extern "C" void kernel_launch(void* const* d_in, const int* in_sizes, int n_in,
                              void* d_out, int out_size) {
    const float* x_enc  = (const float*)d_in[0];
    const float* down_W = (const float*)d_in[1];
    const float* down_b = (const float*)d_in[2];
    const float* conv_W = (const float*)d_in[3];
    const float* conv_b = (const float*)d_in[4];
    const float* up_W   = (const float*)d_in[5];
    const float* up_b   = (const float*)d_in[6];
    const float* bc_g   = (const float*)d_in[7];
    const float* bc_b   = (const float*)d_in[8];
    const float* Wq     = (const float*)d_in[9];
    const float* Wk     = (const float*)d_in[10];
    const float* Wv     = (const float*)d_in[11];
    const float* fcW    = (const float*)d_in[12];
    const float* fcb    = (const float*)d_in[13];
    const float* aln_g  = (const float*)d_in[14];
    const float* aln_b  = (const float*)d_in[15];
    const float* W1     = (const float*)d_in[16];
    const float* b1     = (const float*)d_in[17];
    const float* W2     = (const float*)d_in[18];
    const float* b2     = (const float*)d_in[19];
    const float* fln_g  = (const float*)d_in[20];
    const float* fln_b  = (const float*)d_in[21];
    float* out = (float*)d_out;

    float *c1,*c2,*c3,*pyr,*x,*q,*k,*v,*v2,*fc,*fc2,*xn,*wc,*sim,*psum,*rsum;
    bf16 *wHI,*wLO,*xhi,*xlo,*xnhi,*xnlo,*oohi,*oolo,*hhi,*hlo;
    bf16 *QH,*QL,*KH,*KL,*VTH,*VTL,*PH,*PL;
    unsigned char *smk;
    cudaGetSymbolAddress((void**)&c1,  g_c1);
    cudaGetSymbolAddress((void**)&c2,  g_c2);
    cudaGetSymbolAddress((void**)&c3,  g_c3);
    cudaGetSymbolAddress((void**)&pyr, g_pyr);
    cudaGetSymbolAddress((void**)&x,   g_x);
    cudaGetSymbolAddress((void**)&q,   g_q);
    cudaGetSymbolAddress((void**)&k,   g_k);
    cudaGetSymbolAddress((void**)&v,   g_v);
    cudaGetSymbolAddress((void**)&v2,  g_v2);
    cudaGetSymbolAddress((void**)&fc,  g_fc);
    cudaGetSymbolAddress((void**)&fc2, g_fc2);
    cudaGetSymbolAddress((void**)&xn,  g_xn);
    cudaGetSymbolAddress((void**)&wc,  g_wc);
    cudaGetSymbolAddress((void**)&sim, g_sim);
    cudaGetSymbolAddress((void**)&psum,g_psum);
    cudaGetSymbolAddress((void**)&rsum,g_rsum);
    cudaGetSymbolAddress((void**)&wHI, g_wHI);
    cudaGetSymbolAddress((void**)&wLO, g_wLO);
    cudaGetSymbolAddress((void**)&xhi, g_xhi);
    cudaGetSymbolAddress((void**)&xlo, g_xlo);
    cudaGetSymbolAddress((void**)&xnhi,g_xnhi);
    cudaGetSymbolAddress((void**)&xnlo,g_xnlo);
    cudaGetSymbolAddress((void**)&oohi,g_oohi);
    cudaGetSymbolAddress((void**)&oolo,g_oolo);
    cudaGetSymbolAddress((void**)&hhi, g_hhi);
    cudaGetSymbolAddress((void**)&hlo, g_hlo);
    cudaGetSymbolAddress((void**)&QH,  g_QH);
    cudaGetSymbolAddress((void**)&QL,  g_QL);
    cudaGetSymbolAddress((void**)&KH,  g_KH);
    cudaGetSymbolAddress((void**)&KL,  g_KL);
    cudaGetSymbolAddress((void**)&VTH, g_VTH);
    cudaGetSymbolAddress((void**)&VTL, g_VTL);
    cudaGetSymbolAddress((void**)&PH,  g_PH);
    cudaGetSymbolAddress((void**)&PL,  g_PL);
    cudaGetSymbolAddress((void**)&smk, g_sm);

    cudaFuncSetAttribute(k_mgemm,        cudaFuncAttributeMaxDynamicSharedMemorySize, DSMEM);
    cudaFuncSetAttribute(k_mgemm_qkv,    cudaFuncAttributeMaxDynamicSharedMemorySize, DSMEM);
    cudaFuncSetAttribute(k_mgemm_fc,     cudaFuncAttributeMaxDynamicSharedMemorySize, DSMEM);
    cudaFuncSetAttribute(k_mgemm_sim,    cudaFuncAttributeMaxDynamicSharedMemorySize, DSMEM);
    cudaFuncSetAttribute(k_att_s,        cudaFuncAttributeMaxDynamicSharedMemorySize, DSMEM);
    cudaFuncSetAttribute(k_mgemm_att_pv, cudaFuncAttributeMaxDynamicSharedMemorySize, DSMEM);

    // ---- upfront weight conversions ----
    k_convw<<<(3*2048*512 + 255)/256, 256>>>(conv_W, wc);
    k_cvtB<<<dim3(16,16), dim3(32,8)>>>(down_W, wHI + WOFF_DOWN, wLO + WOFF_DOWN, 512, 512);
    k_cvtB<<<dim3(16,16), dim3(32,8)>>>(up_W,   wHI + WOFF_UP,   wLO + WOFF_UP,   512, 512);
    k_cvtB_multi<<<dim3(16,64,3), dim3(32,8)>>>(wc, wHI + WOFF_CONV, wLO + WOFF_CONV, 2048, 512);
    k_cvtW_qkv12<<<dim3(16,16,12), dim3(32,8)>>>(Wq, Wk, Wv, wHI + WOFF_QKV, wLO + WOFF_QKV);
    k_cvtB_multi<<<dim3(16,16,4), dim3(32,8)>>>(fcW, wHI + WOFF_FC,   wLO + WOFF_FC,   512, 512);
    k_cvtB_multi<<<dim3(16,16,2), dim3(32,8)>>>(W1,  wHI + WOFF_FFN1, wLO + WOFF_FFN1, 512, 512);
    k_cvtB_multi<<<dim3(16,16,2), dim3(32,8)>>>(W2,  wHI + WOFF_FFN2, wLO + WOFF_FFN2, 512, 512);
    k_cvtA<<<(BATCH*1024*512/4 + 255)/256, 256>>>(x_enc, xhi, xlo, BATCH*1024*512/4);

    // ---- bottleneck ----
    k_mgemm<<<dim3(8,32), 256, DSMEM>>>(xhi, xlo, wHI+WOFF_DOWN, wLO+WOFF_DOWN,
            nullptr, oohi, oolo, down_b, BATCH*1024, 512, 512, 0);
    k_mgemm<<<dim3(8,8), 256, DSMEM>>>(oohi, oolo, wHI+WOFF_CONV, wLO+WOFF_CONV,
            c1, xnhi, xnlo, conv_b, BATCH*256, 512, 2048, 2);
    k_mgemm<<<dim3(8,2), 256, DSMEM>>>(xnhi, xnlo, wHI+WOFF_CONV+1048576, wLO+WOFF_CONV+1048576,
            c2, hhi, hlo, conv_b + 512, BATCH*64, 512, 2048, 2);
    k_mgemm<<<dim3(8,1), 256, DSMEM>>>(hhi, hlo, wHI+WOFF_CONV+2097152, wLO+WOFF_CONV+2097152,
            c3, nullptr, nullptr, conv_b + 1024, BATCH*16, 512, 2048, 2);
    k_pyrcat<<<(BATCH*336*512 + 255)/256, 256>>>(c1, c2, c3, xhi, xlo);
    k_mgemm<<<dim3(8,(BATCH*336 + 127)/128), 256, DSMEM>>>(xhi, xlo, wHI+WOFF_UP, wLO+WOFF_UP,
            pyr, nullptr, nullptr, up_b, BATCH*336, 512, 512, 0);
    k_concat_ln<<<NROWS, 256>>>(x_enc, pyr, bc_g, bc_b, x, xhi, xlo);

    for (int l = 0; l < 2; l++) {
        size_t lo_t = ((size_t)l*2 + 0)*512, lo_s = ((size_t)l*2 + 1)*512;

        // semantic mask
        k_rownorm<<<NROWS, 256>>>(x, xn, xnhi, xnlo);
        k_mgemm_sim<<<dim3(16,8,BATCH), 256, DSMEM>>>(xnhi, xnlo, 0,    1024, 0,       sim);
        k_mgemm_sim<<<dim3(4,2,BATCH),  256, DSMEM>>>(xnhi, xnlo, 1024, 256,  1048576, sim);
        dim3 tg(LTOT, BATCH);
        k_topksel<<<tg, 256>>>(xn, sim, smk);

        // QKV x6 fused; q2/k2 written head-split padded bf16 hi/lo directly
        dim3 qg(8, (NROWS + 127)/128, 6);
        k_mgemm_qkv<<<qg, 256, DSMEM>>>(xhi, xlo,
                wHI + WOFF_QKV + (size_t)l*6*262144, wLO + WOFF_QKV + (size_t)l*6*262144,
                q, k, v, v2, QH, QL, KH, KL, NROWS, 512, 512);

        // temporal branch -> hi/lo directly
        dim3 sg(LTOT, BATCH);
        k_tattn<<<sg, 256>>>(q, k, v, oohi, oolo);

        // semantic branch: fused exp-S + rowsum + PV
        {
            k_cvt_vt<<<dim3(LPAD/32, 2, NBH), dim3(32, 8)>>>(v2, VTH, VTL);
            dim3 gs(NJT, (LTOT + 127)/128, NBH);
            k_att_s<<<gs, 256, DSMEM>>>(QH, QL, KH, KL, smk, PH, PL, psum);
            k_rsumfin<<<(NBH*LTOT + 255)/256, 256>>>(psum, rsum);
            dim3 gv(1, (LTOT + 127)/128, NBH);
            k_mgemm_att_pv<<<gv, 256, DSMEM>>>(PH, PL, VTH, VTL, rsum,
                    oohi + (size_t)NROWS*512, oolo + (size_t)NROWS*512);
        }

        // fc x2 fused
        dim3 fg(8, (NROWS + 127)/128, 2);
        k_mgemm_fc<<<fg, 256, DSMEM>>>(oohi, oolo,
                wHI + WOFF_FC + (size_t)l*2*262144, wLO + WOFF_FC + (size_t)l*2*262144,
                fcb, lo_t, lo_s, fc, fc2, NROWS, 512, 512);

        k_lncomb<<<NROWS, 256>>>(fc, fc2, x, xhi, xlo, aln_g, aln_b, lo_t, lo_s);

        // FFN
        size_t fb = (size_t)l*512;
        dim3 ng(8, (NROWS + 127)/128);
        k_mgemm<<<ng, 256, DSMEM>>>(xhi, xlo,
                wHI + WOFF_FFN1 + (size_t)l*262144, wLO + WOFF_FFN1 + (size_t)l*262144,
                nullptr, hhi, hlo, b1 + fb, NROWS, 512, 512, 1);
        k_mgemm<<<ng, 256, DSMEM>>>(hhi, hlo,
                wHI + WOFF_FFN2 + (size_t)l*262144, wLO + WOFF_FFN2 + (size_t)l*262144,
                fc, nullptr, nullptr, b2 + fb, NROWS, 512, 512, 0);
        if (l == 0)
            k_add_ln<<<NROWS, 256>>>(fc, x, fln_g + fb, fln_b + fb, x, xhi, xlo, 1e-6f);
        else
            k_add_ln<<<NROWS, 256>>>(fc, x, fln_g + fb, fln_b + fb, out, nullptr, nullptr, 1e-6f);
    }
}